// round 2
// baseline (speedup 1.0000x reference)
#include <cuda_runtime.h>
#include <math.h>

#define B_  4
#define S_  2048
#define H_  1024
#define NH  16
#define HD  64
#define M_  (B_ * S_)          // 8192 rows

// Scratch (allocation-free, __device__ globals)
__device__ float g_proj[(size_t)M_ * 4 * H_];   // 128 MB : U|V|Q|K
__device__ float g_attn[(size_t)M_ * H_];       // 32 MB
__device__ float g_gate[(size_t)M_ * H_];       // 32 MB

// ---------------------------------------------------------------------------
// Classic SGEMM 128x128x8, 256 threads, 8x8 per-thread microtile.
// C[M,N] = A[M,K] @ B[K,N] + bias[N] (+ resid[M,N] if non-null)
// ---------------------------------------------------------------------------
__global__ __launch_bounds__(256) void sgemm_bias_res(
    const float* __restrict__ A, const float* __restrict__ Bm,
    const float* __restrict__ bias, const float* __restrict__ resid,
    float* __restrict__ C, int M, int N, int K)
{
    __shared__ float As[8][128];
    __shared__ float Bs[8][128];

    const int tid = threadIdx.x;
    const int tx = tid & 15, ty = tid >> 4;
    const int bx = blockIdx.x, by = blockIdx.y;

    const int a_row = tid >> 1, a_col = (tid & 1) * 4;
    const int b_row = tid >> 5, b_col = (tid & 31) * 4;

    const float* Ap = A + (size_t)(by * 128 + a_row) * K + a_col;
    const float* Bp = Bm + (size_t)b_row * N + bx * 128 + b_col;

    float acc[8][8] = {};

    for (int k0 = 0; k0 < K; k0 += 8) {
        float4 av = *(const float4*)(Ap + k0);
        float4 bv = *(const float4*)(Bp + (size_t)k0 * N);
        As[a_col + 0][a_row] = av.x;
        As[a_col + 1][a_row] = av.y;
        As[a_col + 2][a_row] = av.z;
        As[a_col + 3][a_row] = av.w;
        *(float4*)&Bs[b_row][b_col] = bv;   // row pitch 128 floats -> 16B aligned
        __syncthreads();

#pragma unroll
        for (int k = 0; k < 8; k++) {
            float4 a0 = *(const float4*)&As[k][ty * 8];
            float4 a1 = *(const float4*)&As[k][ty * 8 + 4];
            float4 b0 = *(const float4*)&Bs[k][tx * 8];
            float4 b1 = *(const float4*)&Bs[k][tx * 8 + 4];
            float a[8] = {a0.x, a0.y, a0.z, a0.w, a1.x, a1.y, a1.z, a1.w};
            float b[8] = {b0.x, b0.y, b0.z, b0.w, b1.x, b1.y, b1.z, b1.w};
#pragma unroll
            for (int i = 0; i < 8; i++)
#pragma unroll
                for (int j = 0; j < 8; j++)
                    acc[i][j] = fmaf(a[i], b[j], acc[i][j]);
        }
        __syncthreads();
    }

    const int row0 = by * 128 + ty * 8, col0 = bx * 128 + tx * 8;
#pragma unroll
    for (int i = 0; i < 8; i++) {
        size_t off = (size_t)(row0 + i) * N + col0;
#pragma unroll
        for (int j = 0; j < 8; j++) {
            float v = acc[i][j] + bias[col0 + j];
            if (resid) v += resid[off + j];
            C[off + j] = v;
        }
    }
}

// ---------------------------------------------------------------------------
// Sigmoid attention with fused RoPE. One CTA = one (b,h) x 64-row q-block.
// proj layout per row (4096): [U(1024) | V(1024) | Q(1024) | K(1024)],
// head h occupies columns h*64..h*64+63 within each 1024 chunk.
// NOTE: PAD=65 (odd) -> smem rows are NOT 16B aligned; all smem stores to
// padded tiles must be scalar. Global float4 loads stay (16B aligned).
// ---------------------------------------------------------------------------
#define BQ  64
#define BKV 64
#define PAD 65
#define ATTN_SMEM (4 * BQ * PAD * (int)sizeof(float))   // 66,560 B

__global__ __launch_bounds__(256) void attn_kernel(
    const float* __restrict__ proj, float* __restrict__ out)
{
    extern __shared__ float sm[];
    float* Qs = sm;
    float* Ks = Qs + BQ * PAD;
    float* Vs = Ks + BKV * PAD;
    float* Ps = Vs + BKV * PAD;
    __shared__ float invf[32];

    const int tid = threadIdx.x;
    const int qb = blockIdx.x;
    const int bh = blockIdx.y;
    const int b = bh >> 4, h = bh & 15;
    const int q0 = qb * BQ;
    const size_t rowbase = (size_t)b * S_;

    if (tid < 32) invf[tid] = powf(10000.f, -(float)tid / 32.f);

    // Load raw Q tile (vector global load, scalar smem store)
    for (int i = tid; i < BQ * 16; i += 256) {
        int r = i >> 4, c = (i & 15) * 4;
        float4 v = *(const float4*)(proj + (rowbase + q0 + r) * 4096 + 2048 + h * 64 + c);
        float* q = &Qs[r * PAD + c];
        q[0] = v.x; q[1] = v.y; q[2] = v.z; q[3] = v.w;
    }
    __syncthreads();
    // RoPE Q in place, fold in 1/sqrt(hd)=0.125 scale
    for (int i = tid; i < BQ * 32; i += 256) {
        int r = i >> 5, d = i & 31;
        float ang = (float)(q0 + r) * invf[d];
        float sv, cv; sincosf(ang, &sv, &cv);
        float t1 = Qs[r * PAD + d], t2 = Qs[r * PAD + d + 32];
        Qs[r * PAD + d]      = (t1 * cv - t2 * sv) * 0.125f;
        Qs[r * PAD + d + 32] = (t2 * cv + t1 * sv) * 0.125f;
    }

    const int tx = tid & 15, ty = tid >> 4;
    float acc[4][4] = {};

    for (int kb = 0; kb <= qb; kb++) {
        const int k0 = kb * BKV;
        __syncthreads();   // previous iter done with Ks/Vs/Ps; Qs rope visible on iter 0
        for (int i = tid; i < BKV * 16; i += 256) {
            int r = i >> 4, c = (i & 15) * 4;
            const float* base = proj + (rowbase + k0 + r) * 4096 + h * 64 + c;
            float4 kv = *(const float4*)(base + 3072);
            float4 vv = *(const float4*)(base + 1024);
            float* kd = &Ks[r * PAD + c];
            float* vd = &Vs[r * PAD + c];
            kd[0] = kv.x; kd[1] = kv.y; kd[2] = kv.z; kd[3] = kv.w;
            vd[0] = vv.x; vd[1] = vv.y; vd[2] = vv.z; vd[3] = vv.w;
        }
        __syncthreads();
        // RoPE K in place
        for (int i = tid; i < BKV * 32; i += 256) {
            int r = i >> 5, d = i & 31;
            float ang = (float)(k0 + r) * invf[d];
            float sv, cv; sincosf(ang, &sv, &cv);
            float t1 = Ks[r * PAD + d], t2 = Ks[r * PAD + d + 32];
            Ks[r * PAD + d]      = t1 * cv - t2 * sv;
            Ks[r * PAD + d + 32] = t2 * cv + t1 * sv;
        }
        __syncthreads();

        // Scores: 4x4 microtile over (q,k)
        float sc[4][4] = {};
#pragma unroll 8
        for (int d = 0; d < 64; d++) {
            float qv[4], kv[4];
#pragma unroll
            for (int i = 0; i < 4; i++) qv[i] = Qs[(ty * 4 + i) * PAD + d];
#pragma unroll
            for (int j = 0; j < 4; j++) kv[j] = Ks[(tx * 4 + j) * PAD + d];
#pragma unroll
            for (int i = 0; i < 4; i++)
#pragma unroll
                for (int j = 0; j < 4; j++)
                    sc[i][j] = fmaf(qv[i], kv[j], sc[i][j]);
        }
        const bool diag = (kb == qb);
#pragma unroll
        for (int i = 0; i < 4; i++) {
            int qi = ty * 4 + i;
#pragma unroll
            for (int j = 0; j < 4; j++) {
                int ki = tx * 4 + j;
                float p = 1.f / (1.f + __expf(-sc[i][j]));
                if (diag && ki > qi) p = 0.f;
                Ps[qi * PAD + ki] = p;
            }
        }
        __syncthreads();

        // O += P @ V
#pragma unroll 8
        for (int k = 0; k < 64; k++) {
            float pv[4], vv[4];
#pragma unroll
            for (int i = 0; i < 4; i++) pv[i] = Ps[(ty * 4 + i) * PAD + k];
#pragma unroll
            for (int j = 0; j < 4; j++) vv[j] = Vs[k * PAD + tx * 4 + j];
#pragma unroll
            for (int i = 0; i < 4; i++)
#pragma unroll
                for (int j = 0; j < 4; j++)
                    acc[i][j] = fmaf(pv[i], vv[j], acc[i][j]);
        }
    }

#pragma unroll
    for (int i = 0; i < 4; i++) {
        int q = q0 + ty * 4 + i;
#pragma unroll
        for (int j = 0; j < 4; j++)
            out[(rowbase + q) * H_ + h * 64 + tx * 4 + j] = acc[i][j];
    }
}

// ---------------------------------------------------------------------------
// Fused LayerNorm + SiLU(U) gate. One CTA per row.
// ---------------------------------------------------------------------------
__global__ __launch_bounds__(256) void ln_gate_kernel(
    const float* __restrict__ attn, const float* __restrict__ proj,
    const float* __restrict__ g, const float* __restrict__ bb,
    float* __restrict__ out)
{
    const int row = blockIdx.x;
    const int tid = threadIdx.x;
    const float* a = attn + (size_t)row * H_;

    float s = 0.f, s2 = 0.f;
    for (int i = tid; i < H_; i += 256) {
        float v = a[i];
        s += v;
        s2 = fmaf(v, v, s2);
    }
    __shared__ float red[2][8];
#pragma unroll
    for (int o = 16; o; o >>= 1) {
        s  += __shfl_xor_sync(~0u, s,  o);
        s2 += __shfl_xor_sync(~0u, s2, o);
    }
    if ((tid & 31) == 0) { red[0][tid >> 5] = s; red[1][tid >> 5] = s2; }
    __syncthreads();
    if (tid < 32) {
        s  = (tid < 8) ? red[0][tid] : 0.f;
        s2 = (tid < 8) ? red[1][tid] : 0.f;
#pragma unroll
        for (int o = 4; o; o >>= 1) {
            s  += __shfl_xor_sync(~0u, s,  o);
            s2 += __shfl_xor_sync(~0u, s2, o);
        }
        if (tid == 0) { red[0][0] = s; red[1][0] = s2; }
    }
    __syncthreads();
    const float mu  = red[0][0] * (1.f / H_);
    const float var = red[1][0] * (1.f / H_) - mu * mu;
    const float rstd = rsqrtf(var + 1e-8f);

    const float* up = proj + (size_t)row * 4096;   // U chunk at offset 0
    for (int i = tid; i < H_; i += 256) {
        float u = up[i];
        float silu = u / (1.f + __expf(-u));
        out[(size_t)row * H_ + i] = silu * ((a[i] - mu) * rstd * g[i] + bb[i]);
    }
}

// ---------------------------------------------------------------------------
extern "C" void kernel_launch(void* const* d_in, const int* in_sizes, int n_in,
                              void* d_out, int out_size)
{
    const float* x   = (const float*)d_in[0];
    // d_in[1] = attn_mask (causal tril) — implied by the kernel, unused
    const float* Wp  = (const float*)d_in[2];
    const float* bp  = (const float*)d_in[3];
    const float* lng = (const float*)d_in[4];
    const float* lnb = (const float*)d_in[5];
    const float* Wt  = (const float*)d_in[6];
    const float* bt  = (const float*)d_in[7];
    float* out = (float*)d_out;

    float *proj, *attn, *gate;
    cudaGetSymbolAddress((void**)&proj, g_proj);
    cudaGetSymbolAddress((void**)&attn, g_attn);
    cudaGetSymbolAddress((void**)&gate, g_gate);

    cudaFuncSetAttribute(attn_kernel,
                         cudaFuncAttributeMaxDynamicSharedMemorySize, ATTN_SMEM);

    // 1) proj = x @ Wp + bp        [8192,4096]
    {
        dim3 grid(4 * H_ / 128, M_ / 128);
        sgemm_bias_res<<<grid, 256>>>(x, Wp, bp, nullptr, proj, M_, 4 * H_, H_);
    }
    // 2) attention (RoPE + sigmoid + causal)  -> attn [8192,1024]
    {
        dim3 grid(S_ / BQ, B_ * NH);
        attn_kernel<<<grid, 256, ATTN_SMEM>>>(proj, attn);
    }
    // 3) LayerNorm + SiLU gate -> gate [8192,1024]
    ln_gate_kernel<<<M_, 256>>>(attn, proj, lng, lnb, gate);

    // 4) out = x + gate @ Wt + bt
    {
        dim3 grid(H_ / 128, M_ / 128);
        sgemm_bias_res<<<grid, 256>>>(gate, Wt, bt, x, out, M_, H_, H_);
    }
}

// round 4
// speedup vs baseline: 1.6548x; 1.6548x over previous
#include <cuda_runtime.h>
#include <cuda_bf16.h>
#include <math.h>
#include <stdint.h>

#define B_  4
#define S_  2048
#define H_  1024
#define NH  16
#define M_  (B_ * S_)          // 8192 rows

// ------------------------- scratch (__device__ globals) --------------------
__device__ float g_proj[(size_t)M_ * 4 * H_];          // 128 MB : U|V|Q|K (fp32)
__device__ float g_attn[(size_t)M_ * H_];              // 32 MB
__device__ __nv_bfloat16 g_xhi[(size_t)M_ * H_];
__device__ __nv_bfloat16 g_xlo[(size_t)M_ * H_];
__device__ __nv_bfloat16 g_ghi[(size_t)M_ * H_];
__device__ __nv_bfloat16 g_glo[(size_t)M_ * H_];
__device__ __nv_bfloat16 g_WpT_hi[(size_t)4 * H_ * H_];   // Wp^T [4096,1024]
__device__ __nv_bfloat16 g_WpT_lo[(size_t)4 * H_ * H_];
__device__ __nv_bfloat16 g_WtT_hi[(size_t)H_ * H_];       // Wt^T [1024,1024]
__device__ __nv_bfloat16 g_WtT_lo[(size_t)H_ * H_];

// ------------------------- helpers -----------------------------------------
__device__ __forceinline__ uint32_t smem_u32(const void* p) {
    uint32_t a;
    asm("{ .reg .u64 t; cvta.to.shared.u64 t, %1; cvt.u32.u64 %0, t; }"
        : "=r"(a) : "l"(p));
    return a;
}

// 16B-chunk swizzle: row pitch 64B (32 bf16), chunk c in 0..3.
// rows 0..7 reading the same logical chunk hit 8 distinct 16B slots / 128B.
#define SWZ(r, c) ((uint32_t)((r) * 64 + (((c) ^ (((r) >> 1) & 3)) * 16)))

#define CP_ASYNC16(dst, src) \
    asm volatile("cp.async.cg.shared.global [%0], [%1], 16;" :: "r"(dst), "l"(src))
#define CP_COMMIT() asm volatile("cp.async.commit_group;")
#define CP_WAIT1()  asm volatile("cp.async.wait_group 1;")

#define LDSM4(r0, r1, r2, r3, addr) \
    asm volatile("ldmatrix.sync.aligned.m8n8.x4.shared.b16 {%0,%1,%2,%3}, [%4];" \
        : "=r"(r0), "=r"(r1), "=r"(r2), "=r"(r3) : "r"(addr))

#define MMA16816(d, a, b) \
    asm volatile("mma.sync.aligned.m16n8k16.row.col.f32.bf16.bf16.f32 " \
        "{%0,%1,%2,%3}, {%4,%5,%6,%7}, {%8,%9}, {%0,%1,%2,%3};" \
        : "+f"((d)[0]), "+f"((d)[1]), "+f"((d)[2]), "+f"((d)[3]) \
        : "r"((a)[0]), "r"((a)[1]), "r"((a)[2]), "r"((a)[3]), \
          "r"((b)[0]), "r"((b)[1]))

// ---------------------------------------------------------------------------
// split fp32 -> bf16 hi/lo
// ---------------------------------------------------------------------------
__global__ __launch_bounds__(256) void split_f32(
    const float* __restrict__ x, __nv_bfloat16* __restrict__ hi,
    __nv_bfloat16* __restrict__ lo, int n4)
{
    int i = blockIdx.x * blockDim.x + threadIdx.x;
    if (i >= n4) return;
    float4 v = ((const float4*)x)[i];
    float f[4] = {v.x, v.y, v.z, v.w};
    __nv_bfloat16 h[4], l[4];
#pragma unroll
    for (int j = 0; j < 4; j++) {
        h[j] = __float2bfloat16(f[j]);
        l[j] = __float2bfloat16(f[j] - __bfloat162float(h[j]));
    }
    ((uint2*)hi)[i] = *(uint2*)h;
    ((uint2*)lo)[i] = *(uint2*)l;
}

// ---------------------------------------------------------------------------
// transpose W[K,N] -> WT[N,K], split into bf16 hi/lo
// ---------------------------------------------------------------------------
__global__ __launch_bounds__(256) void transpose_split(
    const float* __restrict__ W, __nv_bfloat16* __restrict__ Thi,
    __nv_bfloat16* __restrict__ Tlo, int K, int N)
{
    __shared__ float t[32][33];
    const int tx = threadIdx.x, ty = threadIdx.y;
    const int n0 = blockIdx.x * 32, k0 = blockIdx.y * 32;
#pragma unroll
    for (int j = 0; j < 32; j += 8)
        t[ty + j][tx] = W[(size_t)(k0 + ty + j) * N + n0 + tx];
    __syncthreads();
#pragma unroll
    for (int j = 0; j < 32; j += 8) {
        float v = t[tx][ty + j];
        __nv_bfloat16 h = __float2bfloat16(v);
        __nv_bfloat16 l = __float2bfloat16(v - __bfloat162float(h));
        size_t o = (size_t)(n0 + ty + j) * K + k0 + tx;
        Thi[o] = h;
        Tlo[o] = l;
    }
}

// ---------------------------------------------------------------------------
// HMMA GEMM: C[M,N] = A[M,K] @ (B[N,K])^T + bias (+resid), 3-term bf16 split.
// CTA 128x128, KB=32, 8 warps (4x2), warp tile 32x64, 2-stage cp.async.
// ---------------------------------------------------------------------------
#define STAGE_BYTES 32768
#define OFF_AHI 0
#define OFF_ALO 8192
#define OFF_BHI 16384
#define OFF_BLO 24576
#define GEMM_SMEM (2 * STAGE_BYTES)     // 65536

__device__ __forceinline__ void load_stage(
    uint32_t sbase, int stage,
    const __nv_bfloat16* __restrict__ Ahi, const __nv_bfloat16* __restrict__ Alo,
    const __nv_bfloat16* __restrict__ Bhi, const __nv_bfloat16* __restrict__ Blo,
    int m0, int n0, int k0, int K, int tid)
{
    uint32_t base = sbase + stage * STAGE_BYTES;
#pragma unroll
    for (int h = 0; h < 2; h++) {
        int q = tid + h * 256;
        int r = q >> 2, c = q & 3;
        uint32_t so = SWZ(r, c);
        size_t ga = (size_t)(m0 + r) * K + k0 + c * 8;
        size_t gb = (size_t)(n0 + r) * K + k0 + c * 8;
        CP_ASYNC16(base + OFF_AHI + so, Ahi + ga);
        CP_ASYNC16(base + OFF_ALO + so, Alo + ga);
        CP_ASYNC16(base + OFF_BHI + so, Bhi + gb);
        CP_ASYNC16(base + OFF_BLO + so, Blo + gb);
    }
}

__global__ __launch_bounds__(256) void gemm_hmma(
    const __nv_bfloat16* __restrict__ Ahi, const __nv_bfloat16* __restrict__ Alo,
    const __nv_bfloat16* __restrict__ Bhi, const __nv_bfloat16* __restrict__ Blo,
    const float* __restrict__ bias, const float* __restrict__ resid,
    float* __restrict__ C, int N, int K)
{
    extern __shared__ char sm[];
    const uint32_t sb = smem_u32(sm);
    const int tid = threadIdx.x, wid = tid >> 5, l = tid & 31;
    const int m0 = blockIdx.y * 128, n0 = blockIdx.x * 128;
    const int wm = (wid & 3) * 32, wn = (wid >> 2) * 64;

    float acc[2][8][4] = {};

    const int niter = K / 32;
    load_stage(sb, 0, Ahi, Alo, Bhi, Blo, m0, n0, 0, K, tid);
    CP_COMMIT();

    for (int j = 0; j < niter; j++) {
        if (j + 1 < niter)
            load_stage(sb, (j + 1) & 1, Ahi, Alo, Bhi, Blo, m0, n0, (j + 1) * 32, K, tid);
        CP_COMMIT();
        CP_WAIT1();
        __syncthreads();

        const uint32_t abase_hi = sb + (j & 1) * STAGE_BYTES + OFF_AHI;
        const uint32_t abase_lo = sb + (j & 1) * STAGE_BYTES + OFF_ALO;
        const uint32_t bbase_hi = sb + (j & 1) * STAGE_BYTES + OFF_BHI;
        const uint32_t bbase_lo = sb + (j & 1) * STAGE_BYTES + OFF_BLO;

#pragma unroll
        for (int kk = 0; kk < 2; kk++) {
            uint32_t a_hi[2][4], a_lo[2][4];
#pragma unroll
            for (int mi = 0; mi < 2; mi++) {
                int row = wm + mi * 16 + (l & 15);
                int c = kk * 2 + (l >> 4);
                LDSM4(a_hi[mi][0], a_hi[mi][1], a_hi[mi][2], a_hi[mi][3],
                      abase_hi + SWZ(row, c));
                LDSM4(a_lo[mi][0], a_lo[mi][1], a_lo[mi][2], a_lo[mi][3],
                      abase_lo + SWZ(row, c));
            }
            uint32_t b_hi[8][2], b_lo[8][2];
#pragma unroll
            for (int p = 0; p < 4; p++) {
                int row = wn + p * 16 + ((l >> 4) * 8) + (l & 7);
                int c = kk * 2 + ((l >> 3) & 1);
                LDSM4(b_hi[p * 2][0], b_hi[p * 2][1], b_hi[p * 2 + 1][0], b_hi[p * 2 + 1][1],
                      bbase_hi + SWZ(row, c));
                LDSM4(b_lo[p * 2][0], b_lo[p * 2][1], b_lo[p * 2 + 1][0], b_lo[p * 2 + 1][1],
                      bbase_lo + SWZ(row, c));
            }
#pragma unroll
            for (int mi = 0; mi < 2; mi++)
#pragma unroll
                for (int nj = 0; nj < 8; nj++)
                    MMA16816(acc[mi][nj], a_hi[mi], b_hi[nj]);
#pragma unroll
            for (int mi = 0; mi < 2; mi++)
#pragma unroll
                for (int nj = 0; nj < 8; nj++)
                    MMA16816(acc[mi][nj], a_hi[mi], b_lo[nj]);
#pragma unroll
            for (int mi = 0; mi < 2; mi++)
#pragma unroll
                for (int nj = 0; nj < 8; nj++)
                    MMA16816(acc[mi][nj], a_lo[mi], b_hi[nj]);
        }
        __syncthreads();
    }

    // epilogue: bias (+resid), float2 stores
#pragma unroll
    for (int mi = 0; mi < 2; mi++) {
#pragma unroll
        for (int nj = 0; nj < 8; nj++) {
            int row0 = m0 + wm + mi * 16 + (l >> 2);
            int col  = n0 + wn + nj * 8 + (l & 3) * 2;
            float bx = bias[col], by = bias[col + 1];
            {
                size_t o = (size_t)row0 * N + col;
                float2 v = {acc[mi][nj][0] + bx, acc[mi][nj][1] + by};
                if (resid) { float2 r = *(const float2*)(resid + o); v.x += r.x; v.y += r.y; }
                *(float2*)(C + o) = v;
            }
            {
                size_t o = (size_t)(row0 + 8) * N + col;
                float2 v = {acc[mi][nj][2] + bx, acc[mi][nj][3] + by};
                if (resid) { float2 r = *(const float2*)(resid + o); v.x += r.x; v.y += r.y; }
                *(float2*)(C + o) = v;
            }
        }
    }
}

// ---------------------------------------------------------------------------
// Sigmoid attention with fused RoPE (unchanged from passing R2 kernel)
// ---------------------------------------------------------------------------
#define BQ  64
#define BKV 64
#define PAD 65
#define ATTN_SMEM (4 * BQ * PAD * (int)sizeof(float))

__global__ __launch_bounds__(256) void attn_kernel(
    const float* __restrict__ proj, float* __restrict__ out)
{
    extern __shared__ float smf[];
    float* Qs = smf;
    float* Ks = Qs + BQ * PAD;
    float* Vs = Ks + BKV * PAD;
    float* Ps = Vs + BKV * PAD;
    __shared__ float invf[32];

    const int tid = threadIdx.x;
    const int qb = blockIdx.x;
    const int bh = blockIdx.y;
    const int b = bh >> 4, h = bh & 15;
    const int q0 = qb * BQ;
    const size_t rowbase = (size_t)b * S_;

    if (tid < 32) invf[tid] = powf(10000.f, -(float)tid / 32.f);

    for (int i = tid; i < BQ * 16; i += 256) {
        int r = i >> 4, c = (i & 15) * 4;
        float4 v = *(const float4*)(proj + (rowbase + q0 + r) * 4096 + 2048 + h * 64 + c);
        float* q = &Qs[r * PAD + c];
        q[0] = v.x; q[1] = v.y; q[2] = v.z; q[3] = v.w;
    }
    __syncthreads();
    for (int i = tid; i < BQ * 32; i += 256) {
        int r = i >> 5, d = i & 31;
        float ang = (float)(q0 + r) * invf[d];
        float sv, cv; sincosf(ang, &sv, &cv);
        float t1 = Qs[r * PAD + d], t2 = Qs[r * PAD + d + 32];
        Qs[r * PAD + d]      = (t1 * cv - t2 * sv) * 0.125f;
        Qs[r * PAD + d + 32] = (t2 * cv + t1 * sv) * 0.125f;
    }

    const int tx = tid & 15, ty = tid >> 4;
    float acc[4][4] = {};

    for (int kb = 0; kb <= qb; kb++) {
        const int k0 = kb * BKV;
        __syncthreads();
        for (int i = tid; i < BKV * 16; i += 256) {
            int r = i >> 4, c = (i & 15) * 4;
            const float* base = proj + (rowbase + k0 + r) * 4096 + h * 64 + c;
            float4 kv = *(const float4*)(base + 3072);
            float4 vv = *(const float4*)(base + 1024);
            float* kd = &Ks[r * PAD + c];
            float* vd = &Vs[r * PAD + c];
            kd[0] = kv.x; kd[1] = kv.y; kd[2] = kv.z; kd[3] = kv.w;
            vd[0] = vv.x; vd[1] = vv.y; vd[2] = vv.z; vd[3] = vv.w;
        }
        __syncthreads();
        for (int i = tid; i < BKV * 32; i += 256) {
            int r = i >> 5, d = i & 31;
            float ang = (float)(k0 + r) * invf[d];
            float sv, cv; sincosf(ang, &sv, &cv);
            float t1 = Ks[r * PAD + d], t2 = Ks[r * PAD + d + 32];
            Ks[r * PAD + d]      = t1 * cv - t2 * sv;
            Ks[r * PAD + d + 32] = t2 * cv + t1 * sv;
        }
        __syncthreads();

        float sc[4][4] = {};
#pragma unroll 8
        for (int d = 0; d < 64; d++) {
            float qv[4], kv[4];
#pragma unroll
            for (int i = 0; i < 4; i++) qv[i] = Qs[(ty * 4 + i) * PAD + d];
#pragma unroll
            for (int j = 0; j < 4; j++) kv[j] = Ks[(tx * 4 + j) * PAD + d];
#pragma unroll
            for (int i = 0; i < 4; i++)
#pragma unroll
                for (int j = 0; j < 4; j++)
                    sc[i][j] = fmaf(qv[i], kv[j], sc[i][j]);
        }
        const bool diag = (kb == qb);
#pragma unroll
        for (int i = 0; i < 4; i++) {
            int qi = ty * 4 + i;
#pragma unroll
            for (int j = 0; j < 4; j++) {
                int ki = tx * 4 + j;
                float p = 1.f / (1.f + __expf(-sc[i][j]));
                if (diag && ki > qi) p = 0.f;
                Ps[qi * PAD + ki] = p;
            }
        }
        __syncthreads();

#pragma unroll 8
        for (int k = 0; k < 64; k++) {
            float pv[4], vv[4];
#pragma unroll
            for (int i = 0; i < 4; i++) pv[i] = Ps[(ty * 4 + i) * PAD + k];
#pragma unroll
            for (int j = 0; j < 4; j++) vv[j] = Vs[k * PAD + tx * 4 + j];
#pragma unroll
            for (int i = 0; i < 4; i++)
#pragma unroll
                for (int j = 0; j < 4; j++)
                    acc[i][j] = fmaf(pv[i], vv[j], acc[i][j]);
        }
    }

#pragma unroll
    for (int i = 0; i < 4; i++) {
        int q = q0 + ty * 4 + i;
#pragma unroll
        for (int j = 0; j < 4; j++)
            out[(rowbase + q) * H_ + h * 64 + tx * 4 + j] = acc[i][j];
    }
}

// ---------------------------------------------------------------------------
// Fused LayerNorm + SiLU(U) gate -> bf16 hi/lo split (feeds GEMM2)
// ---------------------------------------------------------------------------
__global__ __launch_bounds__(256) void ln_gate_kernel(
    const float* __restrict__ attn, const float* __restrict__ proj,
    const float* __restrict__ g, const float* __restrict__ bb,
    __nv_bfloat16* __restrict__ ghi, __nv_bfloat16* __restrict__ glo)
{
    const int row = blockIdx.x;
    const int tid = threadIdx.x;
    const float* a = attn + (size_t)row * H_;

    float s = 0.f, s2 = 0.f;
    for (int i = tid; i < H_; i += 256) {
        float v = a[i];
        s += v;
        s2 = fmaf(v, v, s2);
    }
    __shared__ float red[2][8];
#pragma unroll
    for (int o = 16; o; o >>= 1) {
        s  += __shfl_xor_sync(~0u, s,  o);
        s2 += __shfl_xor_sync(~0u, s2, o);
    }
    if ((tid & 31) == 0) { red[0][tid >> 5] = s; red[1][tid >> 5] = s2; }
    __syncthreads();
    if (tid < 32) {
        s  = (tid < 8) ? red[0][tid] : 0.f;
        s2 = (tid < 8) ? red[1][tid] : 0.f;
#pragma unroll
        for (int o = 4; o; o >>= 1) {
            s  += __shfl_xor_sync(~0u, s,  o);
            s2 += __shfl_xor_sync(~0u, s2, o);
        }
        if (tid == 0) { red[0][0] = s; red[1][0] = s2; }
    }
    __syncthreads();
    const float mu  = red[0][0] * (1.f / H_);
    const float var = red[1][0] * (1.f / H_) - mu * mu;
    const float rstd = rsqrtf(var + 1e-8f);

    const float* up = proj + (size_t)row * 4096;
    for (int i = tid; i < H_; i += 256) {
        float u = up[i];
        float silu = u / (1.f + __expf(-u));
        float v = silu * ((a[i] - mu) * rstd * g[i] + bb[i]);
        __nv_bfloat16 h = __float2bfloat16(v);
        size_t o = (size_t)row * H_ + i;
        ghi[o] = h;
        glo[o] = __float2bfloat16(v - __bfloat162float(h));
    }
}

// ---------------------------------------------------------------------------
extern "C" void kernel_launch(void* const* d_in, const int* in_sizes, int n_in,
                              void* d_out, int out_size)
{
    const float* x   = (const float*)d_in[0];
    const float* Wp  = (const float*)d_in[2];
    const float* bp  = (const float*)d_in[3];
    const float* lng = (const float*)d_in[4];
    const float* lnb = (const float*)d_in[5];
    const float* Wt  = (const float*)d_in[6];
    const float* bt  = (const float*)d_in[7];
    float* out = (float*)d_out;

    float *proj, *attn;
    __nv_bfloat16 *xhi, *xlo, *ghi, *glo, *WpTh, *WpTl, *WtTh, *WtTl;
    cudaGetSymbolAddress((void**)&proj, g_proj);
    cudaGetSymbolAddress((void**)&attn, g_attn);
    cudaGetSymbolAddress((void**)&xhi, g_xhi);
    cudaGetSymbolAddress((void**)&xlo, g_xlo);
    cudaGetSymbolAddress((void**)&ghi, g_ghi);
    cudaGetSymbolAddress((void**)&glo, g_glo);
    cudaGetSymbolAddress((void**)&WpTh, g_WpT_hi);
    cudaGetSymbolAddress((void**)&WpTl, g_WpT_lo);
    cudaGetSymbolAddress((void**)&WtTh, g_WtT_hi);
    cudaGetSymbolAddress((void**)&WtTl, g_WtT_lo);

    cudaFuncSetAttribute(attn_kernel,
                         cudaFuncAttributeMaxDynamicSharedMemorySize, ATTN_SMEM);
    cudaFuncSetAttribute(gemm_hmma,
                         cudaFuncAttributeMaxDynamicSharedMemorySize, GEMM_SMEM);

    // 0) splits + weight transposes
    split_f32<<<(M_ * H_ / 4 + 255) / 256, 256>>>(x, xhi, xlo, M_ * H_ / 4);
    transpose_split<<<dim3(4 * H_ / 32, H_ / 32), dim3(32, 8)>>>(Wp, WpTh, WpTl, H_, 4 * H_);
    transpose_split<<<dim3(H_ / 32, H_ / 32), dim3(32, 8)>>>(Wt, WtTh, WtTl, H_, H_);

    // 1) proj = x @ Wp + bp   [8192, 4096]
    gemm_hmma<<<dim3(4 * H_ / 128, M_ / 128), 256, GEMM_SMEM>>>(
        xhi, xlo, WpTh, WpTl, bp, nullptr, proj, 4 * H_, H_);

    // 2) attention -> attn [8192, 1024]
    attn_kernel<<<dim3(S_ / BQ, B_ * NH), 256, ATTN_SMEM>>>(proj, attn);

    // 3) LN + SiLU gate -> bf16 hi/lo
    ln_gate_kernel<<<M_, 256>>>(attn, proj, lng, lnb, ghi, glo);

    // 4) out = x + gate @ Wt + bt
    gemm_hmma<<<dim3(H_ / 128, M_ / 128), 256, GEMM_SMEM>>>(
        ghi, glo, WtTh, WtTl, bt, x, out, H_, H_);
}

// round 6
// speedup vs baseline: 1.9501x; 1.1784x over previous
#include <cuda_runtime.h>
#include <cuda_bf16.h>
#include <math.h>
#include <stdint.h>

#define B_  4
#define S_  2048
#define H_  1024
#define NH  16
#define M_  (B_ * S_)          // 8192 rows

// ------------------------- scratch (__device__ globals) --------------------
__device__ float g_proj[(size_t)M_ * 4 * H_];          // 128 MB : U|V|Q|K (fp32)
__device__ float g_attn[(size_t)M_ * H_];              // 32 MB
__device__ __nv_bfloat16 g_xhi[(size_t)M_ * H_];
__device__ __nv_bfloat16 g_xlo[(size_t)M_ * H_];
__device__ __nv_bfloat16 g_ghi[(size_t)M_ * H_];
__device__ __nv_bfloat16 g_glo[(size_t)M_ * H_];
__device__ __nv_bfloat16 g_WpT_hi[(size_t)4 * H_ * H_];
__device__ __nv_bfloat16 g_WpT_lo[(size_t)4 * H_ * H_];
__device__ __nv_bfloat16 g_WtT_hi[(size_t)H_ * H_];
__device__ __nv_bfloat16 g_WtT_lo[(size_t)H_ * H_];
// attention operands in [b*h][s][64] layout, bf16 hi/lo
__device__ __nv_bfloat16 g_qh[(size_t)M_ * H_];
__device__ __nv_bfloat16 g_ql[(size_t)M_ * H_];
__device__ __nv_bfloat16 g_kh[(size_t)M_ * H_];
__device__ __nv_bfloat16 g_kl[(size_t)M_ * H_];
__device__ __nv_bfloat16 g_vh[(size_t)M_ * H_];
__device__ __nv_bfloat16 g_vl[(size_t)M_ * H_];

// ------------------------- helpers -----------------------------------------
__device__ __forceinline__ uint32_t smem_u32(const void* p) {
    uint32_t a;
    asm("{ .reg .u64 t; cvta.to.shared.u64 t, %1; cvt.u32.u64 %0, t; }"
        : "=r"(a) : "l"(p));
    return a;
}

#define SWZ(r, c) ((uint32_t)((r) * 64 + (((c) ^ (((r) >> 1) & 3)) * 16)))

#define CP_ASYNC16(dst, src) \
    asm volatile("cp.async.cg.shared.global [%0], [%1], 16;" :: "r"(dst), "l"(src))
#define CP_COMMIT() asm volatile("cp.async.commit_group;")
#define CP_WAIT1()  asm volatile("cp.async.wait_group 1;")
#define CP_WAIT0()  asm volatile("cp.async.wait_group 0;")

#define LDSM4(r0, r1, r2, r3, addr) \
    asm volatile("ldmatrix.sync.aligned.m8n8.x4.shared.b16 {%0,%1,%2,%3}, [%4];" \
        : "=r"(r0), "=r"(r1), "=r"(r2), "=r"(r3) : "r"(addr))
#define LDSM4T(r0, r1, r2, r3, addr) \
    asm volatile("ldmatrix.sync.aligned.m8n8.x4.trans.shared.b16 {%0,%1,%2,%3}, [%4];" \
        : "=r"(r0), "=r"(r1), "=r"(r2), "=r"(r3) : "r"(addr))

#define MMA16816(d, a, b) \
    asm volatile("mma.sync.aligned.m16n8k16.row.col.f32.bf16.bf16.f32 " \
        "{%0,%1,%2,%3}, {%4,%5,%6,%7}, {%8,%9}, {%0,%1,%2,%3};" \
        : "+f"((d)[0]), "+f"((d)[1]), "+f"((d)[2]), "+f"((d)[3]) \
        : "r"((a)[0]), "r"((a)[1]), "r"((a)[2]), "r"((a)[3]), \
          "r"((b)[0]), "r"((b)[1]))

// ---------------------------------------------------------------------------
// split fp32 -> bf16 hi/lo
// ---------------------------------------------------------------------------
__global__ __launch_bounds__(256) void split_f32(
    const float* __restrict__ x, __nv_bfloat16* __restrict__ hi,
    __nv_bfloat16* __restrict__ lo, int n4)
{
    int i = blockIdx.x * blockDim.x + threadIdx.x;
    if (i >= n4) return;
    float4 v = ((const float4*)x)[i];
    float f[4] = {v.x, v.y, v.z, v.w};
    __nv_bfloat16 h[4], l[4];
#pragma unroll
    for (int j = 0; j < 4; j++) {
        h[j] = __float2bfloat16(f[j]);
        l[j] = __float2bfloat16(f[j] - __bfloat162float(h[j]));
    }
    ((uint2*)hi)[i] = *(uint2*)h;
    ((uint2*)lo)[i] = *(uint2*)l;
}

// ---------------------------------------------------------------------------
// transpose W[K,N] -> WT[N,K], split into bf16 hi/lo
// ---------------------------------------------------------------------------
__global__ __launch_bounds__(256) void transpose_split(
    const float* __restrict__ W, __nv_bfloat16* __restrict__ Thi,
    __nv_bfloat16* __restrict__ Tlo, int K, int N)
{
    __shared__ float t[32][33];
    const int tx = threadIdx.x, ty = threadIdx.y;
    const int n0 = blockIdx.x * 32, k0 = blockIdx.y * 32;
#pragma unroll
    for (int j = 0; j < 32; j += 8)
        t[ty + j][tx] = W[(size_t)(k0 + ty + j) * N + n0 + tx];
    __syncthreads();
#pragma unroll
    for (int j = 0; j < 32; j += 8) {
        float v = t[tx][ty + j];
        __nv_bfloat16 h = __float2bfloat16(v);
        __nv_bfloat16 l = __float2bfloat16(v - __bfloat162float(h));
        size_t o = (size_t)(n0 + ty + j) * K + k0 + tx;
        Thi[o] = h;
        Tlo[o] = l;
    }
}

// ---------------------------------------------------------------------------
// HMMA GEMM (unchanged from R4 passing version)
// ---------------------------------------------------------------------------
#define STAGE_BYTES 32768
#define OFF_AHI 0
#define OFF_ALO 8192
#define OFF_BHI 16384
#define OFF_BLO 24576
#define GEMM_SMEM (2 * STAGE_BYTES)

__device__ __forceinline__ void load_stage(
    uint32_t sbase, int stage,
    const __nv_bfloat16* __restrict__ Ahi, const __nv_bfloat16* __restrict__ Alo,
    const __nv_bfloat16* __restrict__ Bhi, const __nv_bfloat16* __restrict__ Blo,
    int m0, int n0, int k0, int K, int tid)
{
    uint32_t base = sbase + stage * STAGE_BYTES;
#pragma unroll
    for (int h = 0; h < 2; h++) {
        int q = tid + h * 256;
        int r = q >> 2, c = q & 3;
        uint32_t so = SWZ(r, c);
        size_t ga = (size_t)(m0 + r) * K + k0 + c * 8;
        size_t gb = (size_t)(n0 + r) * K + k0 + c * 8;
        CP_ASYNC16(base + OFF_AHI + so, Ahi + ga);
        CP_ASYNC16(base + OFF_ALO + so, Alo + ga);
        CP_ASYNC16(base + OFF_BHI + so, Bhi + gb);
        CP_ASYNC16(base + OFF_BLO + so, Blo + gb);
    }
}

__global__ __launch_bounds__(256) void gemm_hmma(
    const __nv_bfloat16* __restrict__ Ahi, const __nv_bfloat16* __restrict__ Alo,
    const __nv_bfloat16* __restrict__ Bhi, const __nv_bfloat16* __restrict__ Blo,
    const float* __restrict__ bias, const float* __restrict__ resid,
    float* __restrict__ C, int N, int K)
{
    extern __shared__ char sm[];
    const uint32_t sb = smem_u32(sm);
    const int tid = threadIdx.x, wid = tid >> 5, l = tid & 31;
    const int m0 = blockIdx.y * 128, n0 = blockIdx.x * 128;
    const int wm = (wid & 3) * 32, wn = (wid >> 2) * 64;

    float acc[2][8][4] = {};

    const int niter = K / 32;
    load_stage(sb, 0, Ahi, Alo, Bhi, Blo, m0, n0, 0, K, tid);
    CP_COMMIT();

    for (int j = 0; j < niter; j++) {
        if (j + 1 < niter)
            load_stage(sb, (j + 1) & 1, Ahi, Alo, Bhi, Blo, m0, n0, (j + 1) * 32, K, tid);
        CP_COMMIT();
        CP_WAIT1();
        __syncthreads();

        const uint32_t abase_hi = sb + (j & 1) * STAGE_BYTES + OFF_AHI;
        const uint32_t abase_lo = sb + (j & 1) * STAGE_BYTES + OFF_ALO;
        const uint32_t bbase_hi = sb + (j & 1) * STAGE_BYTES + OFF_BHI;
        const uint32_t bbase_lo = sb + (j & 1) * STAGE_BYTES + OFF_BLO;

#pragma unroll
        for (int kk = 0; kk < 2; kk++) {
            uint32_t a_hi[2][4], a_lo[2][4];
#pragma unroll
            for (int mi = 0; mi < 2; mi++) {
                int row = wm + mi * 16 + (l & 15);
                int c = kk * 2 + (l >> 4);
                LDSM4(a_hi[mi][0], a_hi[mi][1], a_hi[mi][2], a_hi[mi][3],
                      abase_hi + SWZ(row, c));
                LDSM4(a_lo[mi][0], a_lo[mi][1], a_lo[mi][2], a_lo[mi][3],
                      abase_lo + SWZ(row, c));
            }
            uint32_t b_hi[8][2], b_lo[8][2];
#pragma unroll
            for (int p = 0; p < 4; p++) {
                int row = wn + p * 16 + ((l >> 4) * 8) + (l & 7);
                int c = kk * 2 + ((l >> 3) & 1);
                LDSM4(b_hi[p * 2][0], b_hi[p * 2][1], b_hi[p * 2 + 1][0], b_hi[p * 2 + 1][1],
                      bbase_hi + SWZ(row, c));
                LDSM4(b_lo[p * 2][0], b_lo[p * 2][1], b_lo[p * 2 + 1][0], b_lo[p * 2 + 1][1],
                      bbase_lo + SWZ(row, c));
            }
#pragma unroll
            for (int mi = 0; mi < 2; mi++)
#pragma unroll
                for (int nj = 0; nj < 8; nj++)
                    MMA16816(acc[mi][nj], a_hi[mi], b_hi[nj]);
#pragma unroll
            for (int mi = 0; mi < 2; mi++)
#pragma unroll
                for (int nj = 0; nj < 8; nj++)
                    MMA16816(acc[mi][nj], a_hi[mi], b_lo[nj]);
#pragma unroll
            for (int mi = 0; mi < 2; mi++)
#pragma unroll
                for (int nj = 0; nj < 8; nj++)
                    MMA16816(acc[mi][nj], a_lo[mi], b_hi[nj]);
        }
        __syncthreads();
    }

#pragma unroll
    for (int mi = 0; mi < 2; mi++) {
#pragma unroll
        for (int nj = 0; nj < 8; nj++) {
            int row0 = m0 + wm + mi * 16 + (l >> 2);
            int col  = n0 + wn + nj * 8 + (l & 3) * 2;
            float bx = bias[col], by = bias[col + 1];
            {
                size_t o = (size_t)row0 * N + col;
                float2 v = {acc[mi][nj][0] + bx, acc[mi][nj][1] + by};
                if (resid) { float2 r = *(const float2*)(resid + o); v.x += r.x; v.y += r.y; }
                *(float2*)(C + o) = v;
            }
            {
                size_t o = (size_t)(row0 + 8) * N + col;
                float2 v = {acc[mi][nj][2] + bx, acc[mi][nj][3] + by};
                if (resid) { float2 r = *(const float2*)(resid + o); v.x += r.x; v.y += r.y; }
                *(float2*)(C + o) = v;
            }
        }
    }
}

// ---------------------------------------------------------------------------
// Prep: RoPE Q/K once, split Q/K/V into bf16 hi/lo, repack [b*h][s][64].
// One CTA per (b,s) row, 256 threads.
// ---------------------------------------------------------------------------
__global__ __launch_bounds__(256) void rope_split_qkv(
    const float* __restrict__ proj,
    __nv_bfloat16* __restrict__ qh, __nv_bfloat16* __restrict__ ql,
    __nv_bfloat16* __restrict__ kh, __nv_bfloat16* __restrict__ kl,
    __nv_bfloat16* __restrict__ vh, __nv_bfloat16* __restrict__ vl)
{
    const int row = blockIdx.x;            // b*2048 + s
    const int b = row >> 11, s = row & 2047;
    const float* pr = proj + (size_t)row * 4096;
    const int tid = threadIdx.x;

#pragma unroll
    for (int pp = 0; pp < 2; pp++) {
        int p = tid + pp * 256;            // 512 (h,d) pairs
        int h = p >> 5, d = p & 31;
        float inv = powf(10000.f, -(float)d / 32.f);
        float sv, cv; sincosf((float)s * inv, &sv, &cv);
        const float* Qp = pr + 2048 + h * 64 + d;
        const float* Kp = pr + 3072 + h * 64 + d;
        float q1 = Qp[0], q2 = Qp[32];
        float k1 = Kp[0], k2 = Kp[32];
        float qr1 = (q1 * cv - q2 * sv) * 0.125f;
        float qr2 = (q2 * cv + q1 * sv) * 0.125f;
        float kr1 = k1 * cv - k2 * sv;
        float kr2 = k2 * cv + k1 * sv;
        size_t o = ((size_t)(b * 16 + h) * 2048 + s) * 64 + d;
        __nv_bfloat16 t;
        t = __float2bfloat16(qr1); qh[o] = t;      ql[o]      = __float2bfloat16(qr1 - __bfloat162float(t));
        t = __float2bfloat16(qr2); qh[o + 32] = t; ql[o + 32] = __float2bfloat16(qr2 - __bfloat162float(t));
        t = __float2bfloat16(kr1); kh[o] = t;      kl[o]      = __float2bfloat16(kr1 - __bfloat162float(t));
        t = __float2bfloat16(kr2); kh[o + 32] = t; kl[o + 32] = __float2bfloat16(kr2 - __bfloat162float(t));
    }
    // V: 4 elems per thread
    {
        int h = tid >> 4, d = (tid & 15) * 4;
        float4 v = *(const float4*)(pr + 1024 + h * 64 + d);
        float f[4] = {v.x, v.y, v.z, v.w};
        __nv_bfloat16 hh[4], ll[4];
#pragma unroll
        for (int j = 0; j < 4; j++) {
            hh[j] = __float2bfloat16(f[j]);
            ll[j] = __float2bfloat16(f[j] - __bfloat162float(hh[j]));
        }
        size_t o = ((size_t)(b * 16 + h) * 2048 + s) * 64 + d;
        *(uint2*)(vh + o) = *(uint2*)hh;
        *(uint2*)(vl + o) = *(uint2*)ll;
    }
}

// ---------------------------------------------------------------------------
// HMMA sigmoid attention. CTA = (b*h, qb). 8 warps: 4 (q) x 2 (n/d).
// Tiles 64x64, pitch 72 bf16 (144 B) -> conflict-free ldmatrix, no swizzle.
// ---------------------------------------------------------------------------
#define PT 72
#define TB (64 * PT * 2)       // 9216 B per tile
#define OQH 0
#define OQL (TB)
#define OKH (2 * TB)
#define OKL (3 * TB)
#define OVH (4 * TB)
#define OVL (5 * TB)
#define OPH (6 * TB)
#define OPL (7 * TB)
#define ATTN_SMEM (8 * TB)     // 73728 B

__global__ __launch_bounds__(256) void attn_hmma(
    const __nv_bfloat16* __restrict__ qh, const __nv_bfloat16* __restrict__ ql,
    const __nv_bfloat16* __restrict__ kh, const __nv_bfloat16* __restrict__ kl,
    const __nv_bfloat16* __restrict__ vh, const __nv_bfloat16* __restrict__ vl,
    float* __restrict__ out)
{
    extern __shared__ char sm[];
    const uint32_t sb = smem_u32(sm);
    const int tid = threadIdx.x, wid = tid >> 5, l = tid & 31;
    const int bh = blockIdx.x;
    const int qb = (int)gridDim.y - 1 - (int)blockIdx.y;   // big blocks first
    const int q0 = qb * 64;
    const size_t hbase = (size_t)bh << 17;                 // bh * 2048 * 64
    const int wq = wid & 3, wn = wid >> 2;                 // q-tile 16 @ wq*16, n/d 32 @ wn*32

    // ---- load Q tiles ----
#pragma unroll
    for (int it = 0; it < 2; it++) {
        int i = tid + it * 256;            // 512 chunks
        int r = i >> 3, c = i & 7;
        uint32_t so = (uint32_t)(r * 144 + c * 16);
        size_t g = hbase + (size_t)(q0 + r) * 64 + c * 8;
        CP_ASYNC16(sb + OQH + so, qh + g);
        CP_ASYNC16(sb + OQL + so, ql + g);
    }
    CP_COMMIT();
    CP_WAIT0();
    __syncthreads();

    // ---- hoist Q fragments ----
    uint32_t aQh[4][4], aQl[4][4];
#pragma unroll
    for (int ks = 0; ks < 4; ks++) {
        uint32_t ro = (uint32_t)((wq * 16 + (l & 15)) * 144 + (ks * 2 + (l >> 4)) * 16);
        LDSM4(aQh[ks][0], aQh[ks][1], aQh[ks][2], aQh[ks][3], sb + OQH + ro);
        LDSM4(aQl[ks][0], aQl[ks][1], aQl[ks][2], aQl[ks][3], sb + OQL + ro);
    }

    float accO[4][4] = {};

    for (int kb = 0; kb <= qb; kb++) {
        // ---- load K/V tiles ----
#pragma unroll
        for (int it = 0; it < 2; it++) {
            int i = tid + it * 256;
            int r = i >> 3, c = i & 7;
            uint32_t so = (uint32_t)(r * 144 + c * 16);
            size_t g = hbase + (size_t)(kb * 64 + r) * 64 + c * 8;
            CP_ASYNC16(sb + OKH + so, kh + g);
            CP_ASYNC16(sb + OKL + so, kl + g);
            CP_ASYNC16(sb + OVH + so, vh + g);
            CP_ASYNC16(sb + OVL + so, vl + g);
        }
        CP_COMMIT();
        CP_WAIT0();
        __syncthreads();

        // ---- scores ----
        float sc[4][4] = {};
#pragma unroll
        for (int ks = 0; ks < 4; ks++) {
            uint32_t bKh[4][2], bKl[4][2];
#pragma unroll
            for (int g2 = 0; g2 < 2; g2++) {
                int row = wn * 32 + g2 * 16 + ((l >> 4) * 8) + (l & 7);
                uint32_t ro = (uint32_t)(row * 144 + (ks * 2 + ((l >> 3) & 1)) * 16);
                LDSM4(bKh[g2 * 2][0], bKh[g2 * 2][1], bKh[g2 * 2 + 1][0], bKh[g2 * 2 + 1][1],
                      sb + OKH + ro);
                LDSM4(bKl[g2 * 2][0], bKl[g2 * 2][1], bKl[g2 * 2 + 1][0], bKl[g2 * 2 + 1][1],
                      sb + OKL + ro);
            }
#pragma unroll
            for (int nt = 0; nt < 4; nt++) MMA16816(sc[nt], aQh[ks], bKh[nt]);
#pragma unroll
            for (int nt = 0; nt < 4; nt++) MMA16816(sc[nt], aQh[ks], bKl[nt]);
#pragma unroll
            for (int nt = 0; nt < 4; nt++) MMA16816(sc[nt], aQl[ks], bKh[nt]);
        }

        // ---- sigmoid + causal mask + split P to smem ----
        const bool diag = (kb == qb);
#pragma unroll
        for (int nt = 0; nt < 4; nt++) {
#pragma unroll
            for (int half = 0; half < 2; half++) {
                int lq = wq * 16 + (l >> 2) + half * 8;
                int lk = wn * 32 + nt * 8 + (l & 3) * 2;
                float p0 = 1.f / (1.f + __expf(-sc[nt][half * 2]));
                float p1 = 1.f / (1.f + __expf(-sc[nt][half * 2 + 1]));
                if (diag) {
                    if (lk > lq) p0 = 0.f;
                    if (lk + 1 > lq) p1 = 0.f;
                }
                __nv_bfloat16 h0 = __float2bfloat16(p0);
                __nv_bfloat16 h1 = __float2bfloat16(p1);
                __nv_bfloat16 l0 = __float2bfloat16(p0 - __bfloat162float(h0));
                __nv_bfloat16 l1 = __float2bfloat16(p1 - __bfloat162float(h1));
                uint32_t off = (uint32_t)(lq * 144 + lk * 2);
                __nv_bfloat16 hp[2] = {h0, h1}, lp[2] = {l0, l1};
                *(uint32_t*)(sm + OPH + off) = *(uint32_t*)hp;
                *(uint32_t*)(sm + OPL + off) = *(uint32_t*)lp;
            }
        }
        __syncthreads();

        // ---- O += P @ V ----
#pragma unroll
        for (int ks = 0; ks < 4; ks++) {
            uint32_t aPh[4], aPl[4];
            {
                uint32_t ro = (uint32_t)((wq * 16 + (l & 15)) * 144 + (ks * 2 + (l >> 4)) * 16);
                LDSM4(aPh[0], aPh[1], aPh[2], aPh[3], sb + OPH + ro);
                LDSM4(aPl[0], aPl[1], aPl[2], aPl[3], sb + OPL + ro);
            }
            uint32_t bVh[4][2], bVl[4][2];
#pragma unroll
            for (int g2 = 0; g2 < 2; g2++) {
                int row = ks * 16 + (l & 7) + ((l >> 3) & 1) * 8;
                uint32_t ro = (uint32_t)(row * 144 + wn * 64 + g2 * 32 + (l >> 4) * 16);
                LDSM4T(bVh[g2 * 2][0], bVh[g2 * 2][1], bVh[g2 * 2 + 1][0], bVh[g2 * 2 + 1][1],
                       sb + OVH + ro);
                LDSM4T(bVl[g2 * 2][0], bVl[g2 * 2][1], bVl[g2 * 2 + 1][0], bVl[g2 * 2 + 1][1],
                       sb + OVL + ro);
            }
#pragma unroll
            for (int dt = 0; dt < 4; dt++) MMA16816(accO[dt], aPh, bVh[dt]);
#pragma unroll
            for (int dt = 0; dt < 4; dt++) MMA16816(accO[dt], aPh, bVl[dt]);
#pragma unroll
            for (int dt = 0; dt < 4; dt++) MMA16816(accO[dt], aPl, bVh[dt]);
        }
        __syncthreads();
    }

    // ---- epilogue ----
    const int b = bh >> 4, h = bh & 15;
#pragma unroll
    for (int dt = 0; dt < 4; dt++) {
#pragma unroll
        for (int half = 0; half < 2; half++) {
            int q = q0 + wq * 16 + (l >> 2) + half * 8;
            int d = wn * 32 + dt * 8 + (l & 3) * 2;
            size_t o = ((size_t)(b * 2048 + q)) * 1024 + h * 64 + d;
            float2 v = {accO[dt][half * 2], accO[dt][half * 2 + 1]};
            *(float2*)(out + o) = v;
        }
    }
}

// ---------------------------------------------------------------------------
// Fused LayerNorm + SiLU(U) gate -> bf16 hi/lo
// ---------------------------------------------------------------------------
__global__ __launch_bounds__(256) void ln_gate_kernel(
    const float* __restrict__ attn, const float* __restrict__ proj,
    const float* __restrict__ g, const float* __restrict__ bb,
    __nv_bfloat16* __restrict__ ghi, __nv_bfloat16* __restrict__ glo)
{
    const int row = blockIdx.x;
    const int tid = threadIdx.x;
    const float* a = attn + (size_t)row * H_;

    float s = 0.f, s2 = 0.f;
    for (int i = tid; i < H_; i += 256) {
        float v = a[i];
        s += v;
        s2 = fmaf(v, v, s2);
    }
    __shared__ float red[2][8];
#pragma unroll
    for (int o = 16; o; o >>= 1) {
        s  += __shfl_xor_sync(~0u, s,  o);
        s2 += __shfl_xor_sync(~0u, s2, o);
    }
    if ((tid & 31) == 0) { red[0][tid >> 5] = s; red[1][tid >> 5] = s2; }
    __syncthreads();
    if (tid < 32) {
        s  = (tid < 8) ? red[0][tid] : 0.f;
        s2 = (tid < 8) ? red[1][tid] : 0.f;
#pragma unroll
        for (int o = 4; o; o >>= 1) {
            s  += __shfl_xor_sync(~0u, s,  o);
            s2 += __shfl_xor_sync(~0u, s2, o);
        }
        if (tid == 0) { red[0][0] = s; red[1][0] = s2; }
    }
    __syncthreads();
    const float mu  = red[0][0] * (1.f / H_);
    const float var = red[1][0] * (1.f / H_) - mu * mu;
    const float rstd = rsqrtf(var + 1e-8f);

    const float* up = proj + (size_t)row * 4096;
    for (int i = tid; i < H_; i += 256) {
        float u = up[i];
        float silu = u / (1.f + __expf(-u));
        float v = silu * ((a[i] - mu) * rstd * g[i] + bb[i]);
        __nv_bfloat16 h = __float2bfloat16(v);
        size_t o = (size_t)row * H_ + i;
        ghi[o] = h;
        glo[o] = __float2bfloat16(v - __bfloat162float(h));
    }
}

// ---------------------------------------------------------------------------
extern "C" void kernel_launch(void* const* d_in, const int* in_sizes, int n_in,
                              void* d_out, int out_size)
{
    const float* x   = (const float*)d_in[0];
    const float* Wp  = (const float*)d_in[2];
    const float* bp  = (const float*)d_in[3];
    const float* lng = (const float*)d_in[4];
    const float* lnb = (const float*)d_in[5];
    const float* Wt  = (const float*)d_in[6];
    const float* bt  = (const float*)d_in[7];
    float* out = (float*)d_out;

    float *proj, *attn;
    __nv_bfloat16 *xhi, *xlo, *ghi, *glo, *WpTh, *WpTl, *WtTh, *WtTl;
    __nv_bfloat16 *aqh, *aql, *akh, *akl, *avh, *avl;
    cudaGetSymbolAddress((void**)&proj, g_proj);
    cudaGetSymbolAddress((void**)&attn, g_attn);
    cudaGetSymbolAddress((void**)&xhi, g_xhi);
    cudaGetSymbolAddress((void**)&xlo, g_xlo);
    cudaGetSymbolAddress((void**)&ghi, g_ghi);
    cudaGetSymbolAddress((void**)&glo, g_glo);
    cudaGetSymbolAddress((void**)&WpTh, g_WpT_hi);
    cudaGetSymbolAddress((void**)&WpTl, g_WpT_lo);
    cudaGetSymbolAddress((void**)&WtTh, g_WtT_hi);
    cudaGetSymbolAddress((void**)&WtTl, g_WtT_lo);
    cudaGetSymbolAddress((void**)&aqh, g_qh);
    cudaGetSymbolAddress((void**)&aql, g_ql);
    cudaGetSymbolAddress((void**)&akh, g_kh);
    cudaGetSymbolAddress((void**)&akl, g_kl);
    cudaGetSymbolAddress((void**)&avh, g_vh);
    cudaGetSymbolAddress((void**)&avl, g_vl);

    cudaFuncSetAttribute(gemm_hmma,
                         cudaFuncAttributeMaxDynamicSharedMemorySize, GEMM_SMEM);
    cudaFuncSetAttribute(attn_hmma,
                         cudaFuncAttributeMaxDynamicSharedMemorySize, ATTN_SMEM);

    // 0) splits + weight transposes
    split_f32<<<(M_ * H_ / 4 + 255) / 256, 256>>>(x, xhi, xlo, M_ * H_ / 4);
    transpose_split<<<dim3(4 * H_ / 32, H_ / 32), dim3(32, 8)>>>(Wp, WpTh, WpTl, H_, 4 * H_);
    transpose_split<<<dim3(H_ / 32, H_ / 32), dim3(32, 8)>>>(Wt, WtTh, WtTl, H_, H_);

    // 1) proj = x @ Wp + bp   [8192, 4096]
    gemm_hmma<<<dim3(4 * H_ / 128, M_ / 128), 256, GEMM_SMEM>>>(
        xhi, xlo, WpTh, WpTl, bp, nullptr, proj, 4 * H_, H_);

    // 2a) RoPE + split + repack Q/K/V
    rope_split_qkv<<<M_, 256>>>(proj, aqh, aql, akh, akl, avh, avl);

    // 2b) HMMA sigmoid attention -> attn [8192, 1024]
    attn_hmma<<<dim3(B_ * NH, S_ / 64), 256, ATTN_SMEM>>>(
        aqh, aql, akh, akl, avh, avl, attn);

    // 3) LN + SiLU gate -> bf16 hi/lo
    ln_gate_kernel<<<M_, 256>>>(attn, proj, lng, lnb, ghi, glo);

    // 4) out = x + gate @ Wt + bt
    gemm_hmma<<<dim3(H_ / 128, M_ / 128), 256, GEMM_SMEM>>>(
        ghi, glo, WtTh, WtTl, bt, x, out, H_, H_);
}

// round 7
// speedup vs baseline: 3.3204x; 1.7027x over previous
#include <cuda_runtime.h>
#include <cuda_bf16.h>
#include <math.h>
#include <stdint.h>

#define B_  4
#define S_  2048
#define H_  1024
#define NH  16
#define M_  (B_ * S_)          // 8192 rows

// ------------------------- scratch (__device__ globals) --------------------
__device__ float g_proj[(size_t)M_ * 4 * H_];          // 128 MB : U|V|Q|K (fp32)
__device__ float g_attn[(size_t)M_ * H_];              // 32 MB
__device__ __nv_bfloat16 g_xhi[(size_t)M_ * H_];
__device__ __nv_bfloat16 g_xlo[(size_t)M_ * H_];
__device__ __nv_bfloat16 g_ghi[(size_t)M_ * H_];
__device__ __nv_bfloat16 g_glo[(size_t)M_ * H_];
__device__ __nv_bfloat16 g_WpT_hi[(size_t)4 * H_ * H_];
__device__ __nv_bfloat16 g_WpT_lo[(size_t)4 * H_ * H_];
__device__ __nv_bfloat16 g_WtT_hi[(size_t)H_ * H_];
__device__ __nv_bfloat16 g_WtT_lo[(size_t)H_ * H_];
// attention operands in [b*h][s][64] layout, bf16 hi/lo
__device__ __nv_bfloat16 g_qh[(size_t)M_ * H_];
__device__ __nv_bfloat16 g_ql[(size_t)M_ * H_];
__device__ __nv_bfloat16 g_kh[(size_t)M_ * H_];
__device__ __nv_bfloat16 g_kl[(size_t)M_ * H_];
__device__ __nv_bfloat16 g_vh[(size_t)M_ * H_];
__device__ __nv_bfloat16 g_vl[(size_t)M_ * H_];

// ------------------------- helpers -----------------------------------------
__device__ __forceinline__ uint32_t smem_u32(const void* p) {
    uint32_t a;
    asm("{ .reg .u64 t; cvta.to.shared.u64 t, %1; cvt.u32.u64 %0, t; }"
        : "=r"(a) : "l"(p));
    return a;
}

#define SWZ(r, c) ((uint32_t)((r) * 64 + (((c) ^ (((r) >> 1) & 3)) * 16)))

#define CP_ASYNC16(dst, src) \
    asm volatile("cp.async.cg.shared.global [%0], [%1], 16;" :: "r"(dst), "l"(src))
#define CP_COMMIT() asm volatile("cp.async.commit_group;")
#define CP_WAIT1()  asm volatile("cp.async.wait_group 1;")
#define CP_WAIT0()  asm volatile("cp.async.wait_group 0;")

#define LDSM4(r0, r1, r2, r3, addr) \
    asm volatile("ldmatrix.sync.aligned.m8n8.x4.shared.b16 {%0,%1,%2,%3}, [%4];" \
        : "=r"(r0), "=r"(r1), "=r"(r2), "=r"(r3) : "r"(addr))
#define LDSM4T(r0, r1, r2, r3, addr) \
    asm volatile("ldmatrix.sync.aligned.m8n8.x4.trans.shared.b16 {%0,%1,%2,%3}, [%4];" \
        : "=r"(r0), "=r"(r1), "=r"(r2), "=r"(r3) : "r"(addr))

#define MMA16816(d, a, b) \
    asm volatile("mma.sync.aligned.m16n8k16.row.col.f32.bf16.bf16.f32 " \
        "{%0,%1,%2,%3}, {%4,%5,%6,%7}, {%8,%9}, {%0,%1,%2,%3};" \
        : "+f"((d)[0]), "+f"((d)[1]), "+f"((d)[2]), "+f"((d)[3]) \
        : "r"((a)[0]), "r"((a)[1]), "r"((a)[2]), "r"((a)[3]), \
          "r"((b)[0]), "r"((b)[1]))

// ---------------------------------------------------------------------------
// split fp32 -> bf16 hi/lo
// ---------------------------------------------------------------------------
__global__ __launch_bounds__(256) void split_f32(
    const float* __restrict__ x, __nv_bfloat16* __restrict__ hi,
    __nv_bfloat16* __restrict__ lo, int n4)
{
    int i = blockIdx.x * blockDim.x + threadIdx.x;
    if (i >= n4) return;
    float4 v = ((const float4*)x)[i];
    float f[4] = {v.x, v.y, v.z, v.w};
    __nv_bfloat16 h[4], l[4];
#pragma unroll
    for (int j = 0; j < 4; j++) {
        h[j] = __float2bfloat16(f[j]);
        l[j] = __float2bfloat16(f[j] - __bfloat162float(h[j]));
    }
    ((uint2*)hi)[i] = *(uint2*)h;
    ((uint2*)lo)[i] = *(uint2*)l;
}

// ---------------------------------------------------------------------------
// transpose W[K,N] -> WT[N,K], split into bf16 hi/lo
// ---------------------------------------------------------------------------
__global__ __launch_bounds__(256) void transpose_split(
    const float* __restrict__ W, __nv_bfloat16* __restrict__ Thi,
    __nv_bfloat16* __restrict__ Tlo, int K, int N)
{
    __shared__ float t[32][33];
    const int tx = threadIdx.x, ty = threadIdx.y;
    const int n0 = blockIdx.x * 32, k0 = blockIdx.y * 32;
#pragma unroll
    for (int j = 0; j < 32; j += 8)
        t[ty + j][tx] = W[(size_t)(k0 + ty + j) * N + n0 + tx];
    __syncthreads();
#pragma unroll
    for (int j = 0; j < 32; j += 8) {
        float v = t[tx][ty + j];
        __nv_bfloat16 h = __float2bfloat16(v);
        __nv_bfloat16 l = __float2bfloat16(v - __bfloat162float(h));
        size_t o = (size_t)(n0 + ty + j) * K + k0 + tx;
        Thi[o] = h;
        Tlo[o] = l;
    }
}

// ---------------------------------------------------------------------------
// HMMA GEMM: 3-stage cp.async pipeline, one __syncthreads per K-iter.
// ---------------------------------------------------------------------------
#define STAGE_BYTES 32768
#define OFF_AHI 0
#define OFF_ALO 8192
#define OFF_BHI 16384
#define OFF_BLO 24576
#define GEMM_SMEM (3 * STAGE_BYTES)     // 98304

__device__ __forceinline__ void load_stage(
    uint32_t sbase, int stage,
    const __nv_bfloat16* __restrict__ Ahi, const __nv_bfloat16* __restrict__ Alo,
    const __nv_bfloat16* __restrict__ Bhi, const __nv_bfloat16* __restrict__ Blo,
    int m0, int n0, int k0, int K, int tid)
{
    uint32_t base = sbase + stage * STAGE_BYTES;
#pragma unroll
    for (int h = 0; h < 2; h++) {
        int q = tid + h * 256;
        int r = q >> 2, c = q & 3;
        uint32_t so = SWZ(r, c);
        size_t ga = (size_t)(m0 + r) * K + k0 + c * 8;
        size_t gb = (size_t)(n0 + r) * K + k0 + c * 8;
        CP_ASYNC16(base + OFF_AHI + so, Ahi + ga);
        CP_ASYNC16(base + OFF_ALO + so, Alo + ga);
        CP_ASYNC16(base + OFF_BHI + so, Bhi + gb);
        CP_ASYNC16(base + OFF_BLO + so, Blo + gb);
    }
}

__global__ __launch_bounds__(256) void gemm_hmma(
    const __nv_bfloat16* __restrict__ Ahi, const __nv_bfloat16* __restrict__ Alo,
    const __nv_bfloat16* __restrict__ Bhi, const __nv_bfloat16* __restrict__ Blo,
    const float* __restrict__ bias, const float* __restrict__ resid,
    float* __restrict__ C, int N, int K)
{
    extern __shared__ char sm[];
    const uint32_t sb = smem_u32(sm);
    const int tid = threadIdx.x, wid = tid >> 5, l = tid & 31;
    const int m0 = blockIdx.y * 128, n0 = blockIdx.x * 128;
    const int wm = (wid & 3) * 32, wn = (wid >> 2) * 64;

    float acc[2][8][4] = {};

    const int niter = K / 32;     // >= 32 for our shapes
    load_stage(sb, 0, Ahi, Alo, Bhi, Blo, m0, n0, 0, K, tid);
    CP_COMMIT();
    load_stage(sb, 1, Ahi, Alo, Bhi, Blo, m0, n0, 32, K, tid);
    CP_COMMIT();

    int stage = 0;
    for (int j = 0; j < niter; j++) {
        CP_WAIT1();
        __syncthreads();
        if (j + 2 < niter) {
            int s2 = stage + 2; if (s2 >= 3) s2 -= 3;
            load_stage(sb, s2, Ahi, Alo, Bhi, Blo, m0, n0, (j + 2) * 32, K, tid);
        }
        CP_COMMIT();

        const uint32_t base = sb + stage * STAGE_BYTES;
        const uint32_t abase_hi = base + OFF_AHI;
        const uint32_t abase_lo = base + OFF_ALO;
        const uint32_t bbase_hi = base + OFF_BHI;
        const uint32_t bbase_lo = base + OFF_BLO;

#pragma unroll
        for (int kk = 0; kk < 2; kk++) {
            uint32_t a_hi[2][4], a_lo[2][4];
#pragma unroll
            for (int mi = 0; mi < 2; mi++) {
                int row = wm + mi * 16 + (l & 15);
                int c = kk * 2 + (l >> 4);
                LDSM4(a_hi[mi][0], a_hi[mi][1], a_hi[mi][2], a_hi[mi][3],
                      abase_hi + SWZ(row, c));
                LDSM4(a_lo[mi][0], a_lo[mi][1], a_lo[mi][2], a_lo[mi][3],
                      abase_lo + SWZ(row, c));
            }
            uint32_t b_hi[8][2], b_lo[8][2];
#pragma unroll
            for (int p = 0; p < 4; p++) {
                int row = wn + p * 16 + ((l >> 4) * 8) + (l & 7);
                int c = kk * 2 + ((l >> 3) & 1);
                LDSM4(b_hi[p * 2][0], b_hi[p * 2][1], b_hi[p * 2 + 1][0], b_hi[p * 2 + 1][1],
                      bbase_hi + SWZ(row, c));
                LDSM4(b_lo[p * 2][0], b_lo[p * 2][1], b_lo[p * 2 + 1][0], b_lo[p * 2 + 1][1],
                      bbase_lo + SWZ(row, c));
            }
#pragma unroll
            for (int mi = 0; mi < 2; mi++)
#pragma unroll
                for (int nj = 0; nj < 8; nj++)
                    MMA16816(acc[mi][nj], a_hi[mi], b_hi[nj]);
#pragma unroll
            for (int mi = 0; mi < 2; mi++)
#pragma unroll
                for (int nj = 0; nj < 8; nj++)
                    MMA16816(acc[mi][nj], a_hi[mi], b_lo[nj]);
#pragma unroll
            for (int mi = 0; mi < 2; mi++)
#pragma unroll
                for (int nj = 0; nj < 8; nj++)
                    MMA16816(acc[mi][nj], a_lo[mi], b_hi[nj]);
        }
        stage++; if (stage >= 3) stage -= 3;
    }

#pragma unroll
    for (int mi = 0; mi < 2; mi++) {
#pragma unroll
        for (int nj = 0; nj < 8; nj++) {
            int row0 = m0 + wm + mi * 16 + (l >> 2);
            int col  = n0 + wn + nj * 8 + (l & 3) * 2;
            float bx = bias[col], by = bias[col + 1];
            {
                size_t o = (size_t)row0 * N + col;
                float2 v = {acc[mi][nj][0] + bx, acc[mi][nj][1] + by};
                if (resid) { float2 r = *(const float2*)(resid + o); v.x += r.x; v.y += r.y; }
                *(float2*)(C + o) = v;
            }
            {
                size_t o = (size_t)(row0 + 8) * N + col;
                float2 v = {acc[mi][nj][2] + bx, acc[mi][nj][3] + by};
                if (resid) { float2 r = *(const float2*)(resid + o); v.x += r.x; v.y += r.y; }
                *(float2*)(C + o) = v;
            }
        }
    }
}

// ---------------------------------------------------------------------------
// Prep: RoPE Q/K once, split Q/K/V into bf16 hi/lo, repack [b*h][s][64].
// ---------------------------------------------------------------------------
__global__ __launch_bounds__(256) void rope_split_qkv(
    const float* __restrict__ proj,
    __nv_bfloat16* __restrict__ qh, __nv_bfloat16* __restrict__ ql,
    __nv_bfloat16* __restrict__ kh, __nv_bfloat16* __restrict__ kl,
    __nv_bfloat16* __restrict__ vh, __nv_bfloat16* __restrict__ vl)
{
    const int row = blockIdx.x;            // b*2048 + s
    const int b = row >> 11, s = row & 2047;
    const float* pr = proj + (size_t)row * 4096;
    const int tid = threadIdx.x;

#pragma unroll
    for (int pp = 0; pp < 2; pp++) {
        int p = tid + pp * 256;            // 512 (h,d) pairs
        int h = p >> 5, d = p & 31;
        float inv = powf(10000.f, -(float)d / 32.f);
        float sv, cv; sincosf((float)s * inv, &sv, &cv);
        const float* Qp = pr + 2048 + h * 64 + d;
        const float* Kp = pr + 3072 + h * 64 + d;
        float q1 = Qp[0], q2 = Qp[32];
        float k1 = Kp[0], k2 = Kp[32];
        float qr1 = (q1 * cv - q2 * sv) * 0.125f;
        float qr2 = (q2 * cv + q1 * sv) * 0.125f;
        float kr1 = k1 * cv - k2 * sv;
        float kr2 = k2 * cv + k1 * sv;
        size_t o = ((size_t)(b * 16 + h) * 2048 + s) * 64 + d;
        __nv_bfloat16 t;
        t = __float2bfloat16(qr1); qh[o] = t;      ql[o]      = __float2bfloat16(qr1 - __bfloat162float(t));
        t = __float2bfloat16(qr2); qh[o + 32] = t; ql[o + 32] = __float2bfloat16(qr2 - __bfloat162float(t));
        t = __float2bfloat16(kr1); kh[o] = t;      kl[o]      = __float2bfloat16(kr1 - __bfloat162float(t));
        t = __float2bfloat16(kr2); kh[o + 32] = t; kl[o + 32] = __float2bfloat16(kr2 - __bfloat162float(t));
    }
    {
        int h = tid >> 4, d = (tid & 15) * 4;
        float4 v = *(const float4*)(pr + 1024 + h * 64 + d);
        float f[4] = {v.x, v.y, v.z, v.w};
        __nv_bfloat16 hh[4], ll[4];
#pragma unroll
        for (int j = 0; j < 4; j++) {
            hh[j] = __float2bfloat16(f[j]);
            ll[j] = __float2bfloat16(f[j] - __bfloat162float(hh[j]));
        }
        size_t o = ((size_t)(b * 16 + h) * 2048 + s) * 64 + d;
        *(uint2*)(vh + o) = *(uint2*)hh;
        *(uint2*)(vl + o) = *(uint2*)ll;
    }
}

// ---------------------------------------------------------------------------
// HMMA sigmoid attention, 128-row Q tile. CTA = (b*h, qbi). 8 warps:
// warp (wq, wn) owns q rows wq*32..+31 and kv/d cols wn*32..+31.
// Pitch 144 B rows -> conflict-free ldmatrix.
// ---------------------------------------------------------------------------
#define OQH2 0
#define OQL2 18432
#define OKH2 36864
#define OKL2 46080
#define OVH2 55296
#define OVL2 64512
#define OPH2 73728
#define OPL2 92160
#define ATTN_SMEM (110592)

__global__ __launch_bounds__(256) void attn_hmma(
    const __nv_bfloat16* __restrict__ qh, const __nv_bfloat16* __restrict__ ql,
    const __nv_bfloat16* __restrict__ kh, const __nv_bfloat16* __restrict__ kl,
    const __nv_bfloat16* __restrict__ vh, const __nv_bfloat16* __restrict__ vl,
    float* __restrict__ out)
{
    extern __shared__ char sm[];
    const uint32_t sb = smem_u32(sm);
    const int tid = threadIdx.x, wid = tid >> 5, l = tid & 31;
    const int bh = blockIdx.x;
    const int qbi = (int)gridDim.y - 1 - (int)blockIdx.y;   // big blocks first
    const int q0 = qbi * 128;
    const size_t hbase = (size_t)bh << 17;                  // bh * 2048 * 64
    const int wq = wid & 3, wn = wid >> 2;

    // ---- load Q tiles (128 x 64 bf16, hi/lo) ----
#pragma unroll
    for (int it = 0; it < 4; it++) {
        int i = tid + it * 256;            // 1024 chunks
        int r = i >> 3, c = i & 7;
        uint32_t so = (uint32_t)(r * 144 + c * 16);
        size_t g = hbase + (size_t)(q0 + r) * 64 + c * 8;
        CP_ASYNC16(sb + OQH2 + so, qh + g);
        CP_ASYNC16(sb + OQL2 + so, ql + g);
    }
    CP_COMMIT();
    CP_WAIT0();
    __syncthreads();

    float accO[2][4][4] = {};
    const int nkb = 2 * qbi + 2;

    for (int kb = 0; kb < nkb; kb++) {
        const int k0 = kb * 64;
        // ---- load K/V tiles ----
#pragma unroll
        for (int it = 0; it < 2; it++) {
            int i = tid + it * 256;
            int r = i >> 3, c = i & 7;
            uint32_t so = (uint32_t)(r * 144 + c * 16);
            size_t g = hbase + (size_t)(k0 + r) * 64 + c * 8;
            CP_ASYNC16(sb + OKH2 + so, kh + g);
            CP_ASYNC16(sb + OKL2 + so, kl + g);
            CP_ASYNC16(sb + OVH2 + so, vh + g);
            CP_ASYNC16(sb + OVL2 + so, vl + g);
        }
        CP_COMMIT();
        CP_WAIT0();
        __syncthreads();

        // ---- scores ----
        float sc[2][4][4] = {};
#pragma unroll
        for (int ks = 0; ks < 4; ks++) {
            uint32_t aQh[2][4], aQl[2][4];
#pragma unroll
            for (int mi = 0; mi < 2; mi++) {
                uint32_t ro = (uint32_t)((wq * 32 + mi * 16 + (l & 15)) * 144 +
                                         (ks * 2 + (l >> 4)) * 16);
                LDSM4(aQh[mi][0], aQh[mi][1], aQh[mi][2], aQh[mi][3], sb + OQH2 + ro);
                LDSM4(aQl[mi][0], aQl[mi][1], aQl[mi][2], aQl[mi][3], sb + OQL2 + ro);
            }
            uint32_t bKh[4][2], bKl[4][2];
#pragma unroll
            for (int g2 = 0; g2 < 2; g2++) {
                int row = wn * 32 + g2 * 16 + ((l >> 4) * 8) + (l & 7);
                uint32_t ro = (uint32_t)(row * 144 + (ks * 2 + ((l >> 3) & 1)) * 16);
                LDSM4(bKh[g2 * 2][0], bKh[g2 * 2][1], bKh[g2 * 2 + 1][0], bKh[g2 * 2 + 1][1],
                      sb + OKH2 + ro);
                LDSM4(bKl[g2 * 2][0], bKl[g2 * 2][1], bKl[g2 * 2 + 1][0], bKl[g2 * 2 + 1][1],
                      sb + OKL2 + ro);
            }
#pragma unroll
            for (int mi = 0; mi < 2; mi++)
#pragma unroll
                for (int nt = 0; nt < 4; nt++) MMA16816(sc[mi][nt], aQh[mi], bKh[nt]);
#pragma unroll
            for (int mi = 0; mi < 2; mi++)
#pragma unroll
                for (int nt = 0; nt < 4; nt++) MMA16816(sc[mi][nt], aQh[mi], bKl[nt]);
#pragma unroll
            for (int mi = 0; mi < 2; mi++)
#pragma unroll
                for (int nt = 0; nt < 4; nt++) MMA16816(sc[mi][nt], aQl[mi], bKh[nt]);
        }

        // ---- sigmoid + causal mask + split P to smem ----
        const bool edge = (kb >= 2 * qbi);
#pragma unroll
        for (int mi = 0; mi < 2; mi++) {
#pragma unroll
            for (int nt = 0; nt < 4; nt++) {
#pragma unroll
                for (int half = 0; half < 2; half++) {
                    int lq = wq * 32 + mi * 16 + (l >> 2) + half * 8;
                    int lk = wn * 32 + nt * 8 + (l & 3) * 2;
                    float p0 = __fdividef(1.f, 1.f + __expf(-sc[mi][nt][half * 2]));
                    float p1 = __fdividef(1.f, 1.f + __expf(-sc[mi][nt][half * 2 + 1]));
                    if (edge) {
                        if (k0 + lk > q0 + lq) p0 = 0.f;
                        if (k0 + lk + 1 > q0 + lq) p1 = 0.f;
                    }
                    __nv_bfloat16 h0 = __float2bfloat16(p0);
                    __nv_bfloat16 h1 = __float2bfloat16(p1);
                    __nv_bfloat16 l0 = __float2bfloat16(p0 - __bfloat162float(h0));
                    __nv_bfloat16 l1 = __float2bfloat16(p1 - __bfloat162float(h1));
                    uint32_t off = (uint32_t)(lq * 144 + lk * 2);
                    __nv_bfloat16 hp[2] = {h0, h1}, lp[2] = {l0, l1};
                    *(uint32_t*)(sm + OPH2 + off) = *(uint32_t*)hp;
                    *(uint32_t*)(sm + OPL2 + off) = *(uint32_t*)lp;
                }
            }
        }
        __syncthreads();

        // ---- O += P @ V ----
#pragma unroll
        for (int ks = 0; ks < 4; ks++) {
            uint32_t aPh[2][4], aPl[2][4];
#pragma unroll
            for (int mi = 0; mi < 2; mi++) {
                uint32_t ro = (uint32_t)((wq * 32 + mi * 16 + (l & 15)) * 144 +
                                         (ks * 2 + (l >> 4)) * 16);
                LDSM4(aPh[mi][0], aPh[mi][1], aPh[mi][2], aPh[mi][3], sb + OPH2 + ro);
                LDSM4(aPl[mi][0], aPl[mi][1], aPl[mi][2], aPl[mi][3], sb + OPL2 + ro);
            }
            uint32_t bVh[4][2], bVl[4][2];
#pragma unroll
            for (int g2 = 0; g2 < 2; g2++) {
                int row = ks * 16 + (l & 7) + ((l >> 3) & 1) * 8;
                uint32_t ro = (uint32_t)(row * 144 + wn * 64 + g2 * 32 + (l >> 4) * 16);
                LDSM4T(bVh[g2 * 2][0], bVh[g2 * 2][1], bVh[g2 * 2 + 1][0], bVh[g2 * 2 + 1][1],
                       sb + OVH2 + ro);
                LDSM4T(bVl[g2 * 2][0], bVl[g2 * 2][1], bVl[g2 * 2 + 1][0], bVl[g2 * 2 + 1][1],
                       sb + OVL2 + ro);
            }
#pragma unroll
            for (int mi = 0; mi < 2; mi++)
#pragma unroll
                for (int dt = 0; dt < 4; dt++) MMA16816(accO[mi][dt], aPh[mi], bVh[dt]);
#pragma unroll
            for (int mi = 0; mi < 2; mi++)
#pragma unroll
                for (int dt = 0; dt < 4; dt++) MMA16816(accO[mi][dt], aPh[mi], bVl[dt]);
#pragma unroll
            for (int mi = 0; mi < 2; mi++)
#pragma unroll
                for (int dt = 0; dt < 4; dt++) MMA16816(accO[mi][dt], aPl[mi], bVh[dt]);
        }
        __syncthreads();
    }

    // ---- epilogue ----
    const int b = bh >> 4, h = bh & 15;
#pragma unroll
    for (int mi = 0; mi < 2; mi++) {
#pragma unroll
        for (int dt = 0; dt < 4; dt++) {
#pragma unroll
            for (int half = 0; half < 2; half++) {
                int q = q0 + wq * 32 + mi * 16 + (l >> 2) + half * 8;
                int d = wn * 32 + dt * 8 + (l & 3) * 2;
                size_t o = ((size_t)(b * 2048 + q)) * 1024 + h * 64 + d;
                float2 v = {accO[mi][dt][half * 2], accO[mi][dt][half * 2 + 1]};
                *(float2*)(out + o) = v;
            }
        }
    }
}

// ---------------------------------------------------------------------------
// Fused LayerNorm + SiLU(U) gate -> bf16 hi/lo
// ---------------------------------------------------------------------------
__global__ __launch_bounds__(256) void ln_gate_kernel(
    const float* __restrict__ attn, const float* __restrict__ proj,
    const float* __restrict__ g, const float* __restrict__ bb,
    __nv_bfloat16* __restrict__ ghi, __nv_bfloat16* __restrict__ glo)
{
    const int row = blockIdx.x;
    const int tid = threadIdx.x;
    const float* a = attn + (size_t)row * H_;

    float s = 0.f, s2 = 0.f;
    for (int i = tid; i < H_; i += 256) {
        float v = a[i];
        s += v;
        s2 = fmaf(v, v, s2);
    }
    __shared__ float red[2][8];
#pragma unroll
    for (int o = 16; o; o >>= 1) {
        s  += __shfl_xor_sync(~0u, s,  o);
        s2 += __shfl_xor_sync(~0u, s2, o);
    }
    if ((tid & 31) == 0) { red[0][tid >> 5] = s; red[1][tid >> 5] = s2; }
    __syncthreads();
    if (tid < 32) {
        s  = (tid < 8) ? red[0][tid] : 0.f;
        s2 = (tid < 8) ? red[1][tid] : 0.f;
#pragma unroll
        for (int o = 4; o; o >>= 1) {
            s  += __shfl_xor_sync(~0u, s,  o);
            s2 += __shfl_xor_sync(~0u, s2, o);
        }
        if (tid == 0) { red[0][0] = s; red[1][0] = s2; }
    }
    __syncthreads();
    const float mu  = red[0][0] * (1.f / H_);
    const float var = red[1][0] * (1.f / H_) - mu * mu;
    const float rstd = rsqrtf(var + 1e-8f);

    const float* up = proj + (size_t)row * 4096;
    for (int i = tid; i < H_; i += 256) {
        float u = up[i];
        float silu = u * __fdividef(1.f, 1.f + __expf(-u));
        float v = silu * ((a[i] - mu) * rstd * g[i] + bb[i]);
        __nv_bfloat16 h = __float2bfloat16(v);
        size_t o = (size_t)row * H_ + i;
        ghi[o] = h;
        glo[o] = __float2bfloat16(v - __bfloat162float(h));
    }
}

// ---------------------------------------------------------------------------
extern "C" void kernel_launch(void* const* d_in, const int* in_sizes, int n_in,
                              void* d_out, int out_size)
{
    const float* x   = (const float*)d_in[0];
    const float* Wp  = (const float*)d_in[2];
    const float* bp  = (const float*)d_in[3];
    const float* lng = (const float*)d_in[4];
    const float* lnb = (const float*)d_in[5];
    const float* Wt  = (const float*)d_in[6];
    const float* bt  = (const float*)d_in[7];
    float* out = (float*)d_out;

    float *proj, *attn;
    __nv_bfloat16 *xhi, *xlo, *ghi, *glo, *WpTh, *WpTl, *WtTh, *WtTl;
    __nv_bfloat16 *aqh, *aql, *akh, *akl, *avh, *avl;
    cudaGetSymbolAddress((void**)&proj, g_proj);
    cudaGetSymbolAddress((void**)&attn, g_attn);
    cudaGetSymbolAddress((void**)&xhi, g_xhi);
    cudaGetSymbolAddress((void**)&xlo, g_xlo);
    cudaGetSymbolAddress((void**)&ghi, g_ghi);
    cudaGetSymbolAddress((void**)&glo, g_glo);
    cudaGetSymbolAddress((void**)&WpTh, g_WpT_hi);
    cudaGetSymbolAddress((void**)&WpTl, g_WpT_lo);
    cudaGetSymbolAddress((void**)&WtTh, g_WtT_hi);
    cudaGetSymbolAddress((void**)&WtTl, g_WtT_lo);
    cudaGetSymbolAddress((void**)&aqh, g_qh);
    cudaGetSymbolAddress((void**)&aql, g_ql);
    cudaGetSymbolAddress((void**)&akh, g_kh);
    cudaGetSymbolAddress((void**)&akl, g_kl);
    cudaGetSymbolAddress((void**)&avh, g_vh);
    cudaGetSymbolAddress((void**)&avl, g_vl);

    cudaFuncSetAttribute(gemm_hmma,
                         cudaFuncAttributeMaxDynamicSharedMemorySize, GEMM_SMEM);
    cudaFuncSetAttribute(attn_hmma,
                         cudaFuncAttributeMaxDynamicSharedMemorySize, ATTN_SMEM);

    // 0) splits + weight transposes
    split_f32<<<(M_ * H_ / 4 + 255) / 256, 256>>>(x, xhi, xlo, M_ * H_ / 4);
    transpose_split<<<dim3(4 * H_ / 32, H_ / 32), dim3(32, 8)>>>(Wp, WpTh, WpTl, H_, 4 * H_);
    transpose_split<<<dim3(H_ / 32, H_ / 32), dim3(32, 8)>>>(Wt, WtTh, WtTl, H_, H_);

    // 1) proj = x @ Wp + bp   [8192, 4096]
    gemm_hmma<<<dim3(4 * H_ / 128, M_ / 128), 256, GEMM_SMEM>>>(
        xhi, xlo, WpTh, WpTl, bp, nullptr, proj, 4 * H_, H_);

    // 2a) RoPE + split + repack Q/K/V
    rope_split_qkv<<<M_, 256>>>(proj, aqh, aql, akh, akl, avh, avl);

    // 2b) HMMA sigmoid attention -> attn [8192, 1024]
    attn_hmma<<<dim3(B_ * NH, S_ / 128), 256, ATTN_SMEM>>>(
        aqh, aql, akh, akl, avh, avl, attn);

    // 3) LN + SiLU gate -> bf16 hi/lo
    ln_gate_kernel<<<M_, 256>>>(attn, proj, lng, lnb, ghi, glo);

    // 4) out = x + gate @ Wt + bt
    gemm_hmma<<<dim3(H_ / 128, M_ / 128), 256, GEMM_SMEM>>>(
        ghi, glo, WtTh, WtTl, bt, x, out, H_, H_);
}

// round 8
// speedup vs baseline: 4.6252x; 1.3930x over previous
#include <cuda_runtime.h>
#include <cuda_fp16.h>
#include <math.h>
#include <stdint.h>

#define B_  4
#define S_  2048
#define H_  1024
#define NH  16
#define M_  (B_ * S_)          // 8192 rows

// ------------------------- scratch (__device__ globals) --------------------
__device__ float g_proj[(size_t)M_ * 4 * H_];          // 128 MB : U|V|Q|K (fp32)
__device__ float g_attn[(size_t)M_ * H_];              // 32 MB
__device__ __half g_xhi[(size_t)M_ * H_];
__device__ __half g_xlo[(size_t)M_ * H_];
__device__ __half g_ghi[(size_t)M_ * H_];
__device__ __half g_glo[(size_t)M_ * H_];
__device__ __half g_WpT_hi[(size_t)4 * H_ * H_];       // Wp^T [4096,1024] fp16
__device__ __half g_WtT_hi[(size_t)H_ * H_];           // Wt^T [1024,1024] fp16
// attention operands in [b*h][s][64] layout
__device__ __half g_qh[(size_t)M_ * H_];
__device__ __half g_ql[(size_t)M_ * H_];
__device__ __half g_kh[(size_t)M_ * H_];
__device__ __half g_vh[(size_t)M_ * H_];

// ------------------------- helpers -----------------------------------------
__device__ __forceinline__ uint32_t smem_u32(const void* p) {
    uint32_t a;
    asm("{ .reg .u64 t; cvta.to.shared.u64 t, %1; cvt.u32.u64 %0, t; }"
        : "=r"(a) : "l"(p));
    return a;
}

#define SWZ(r, c) ((uint32_t)((r) * 64 + (((c) ^ (((r) >> 1) & 3)) * 16)))

#define CP_ASYNC16(dst, src) \
    asm volatile("cp.async.cg.shared.global [%0], [%1], 16;" :: "r"(dst), "l"(src))
#define CP_COMMIT() asm volatile("cp.async.commit_group;")
#define CP_WAIT1()  asm volatile("cp.async.wait_group 1;")
#define CP_WAIT0()  asm volatile("cp.async.wait_group 0;")

#define LDSM4(r0, r1, r2, r3, addr) \
    asm volatile("ldmatrix.sync.aligned.m8n8.x4.shared.b16 {%0,%1,%2,%3}, [%4];" \
        : "=r"(r0), "=r"(r1), "=r"(r2), "=r"(r3) : "r"(addr))
#define LDSM4T(r0, r1, r2, r3, addr) \
    asm volatile("ldmatrix.sync.aligned.m8n8.x4.trans.shared.b16 {%0,%1,%2,%3}, [%4];" \
        : "=r"(r0), "=r"(r1), "=r"(r2), "=r"(r3) : "r"(addr))

#define MMA16816(d, a, b) \
    asm volatile("mma.sync.aligned.m16n8k16.row.col.f32.f16.f16.f32 " \
        "{%0,%1,%2,%3}, {%4,%5,%6,%7}, {%8,%9}, {%0,%1,%2,%3};" \
        : "+f"((d)[0]), "+f"((d)[1]), "+f"((d)[2]), "+f"((d)[3]) \
        : "r"((a)[0]), "r"((a)[1]), "r"((a)[2]), "r"((a)[3]), \
          "r"((b)[0]), "r"((b)[1]))

// ---------------------------------------------------------------------------
// split fp32 -> fp16 hi/lo
// ---------------------------------------------------------------------------
__global__ __launch_bounds__(256) void split_f32(
    const float* __restrict__ x, __half* __restrict__ hi,
    __half* __restrict__ lo, int n4)
{
    int i = blockIdx.x * blockDim.x + threadIdx.x;
    if (i >= n4) return;
    float4 v = ((const float4*)x)[i];
    float f[4] = {v.x, v.y, v.z, v.w};
    __half h[4], l[4];
#pragma unroll
    for (int j = 0; j < 4; j++) {
        h[j] = __float2half(f[j]);
        l[j] = __float2half(f[j] - __half2float(h[j]));
    }
    ((uint2*)hi)[i] = *(uint2*)h;
    ((uint2*)lo)[i] = *(uint2*)l;
}

// ---------------------------------------------------------------------------
// transpose W[K,N] -> WT[N,K] fp16 (hi only)
// ---------------------------------------------------------------------------
__global__ __launch_bounds__(256) void transpose_half(
    const float* __restrict__ W, __half* __restrict__ Thi, int K, int N)
{
    __shared__ float t[32][33];
    const int tx = threadIdx.x, ty = threadIdx.y;
    const int n0 = blockIdx.x * 32, k0 = blockIdx.y * 32;
#pragma unroll
    for (int j = 0; j < 32; j += 8)
        t[ty + j][tx] = W[(size_t)(k0 + ty + j) * N + n0 + tx];
    __syncthreads();
#pragma unroll
    for (int j = 0; j < 32; j += 8)
        Thi[(size_t)(n0 + ty + j) * K + k0 + tx] = __float2half(t[tx][ty + j]);
}

// ---------------------------------------------------------------------------
// HMMA GEMM fp16 2-term: C = (Ahi+Alo) @ Bhi^T + bias (+resid)
// CTA 128x128, KB=32, 3-stage cp.async pipeline.
// ---------------------------------------------------------------------------
#define STAGE_BYTES 24576
#define OFF_AHI 0
#define OFF_ALO 8192
#define OFF_BHI 16384
#define GEMM_SMEM (3 * STAGE_BYTES)     // 73728

__device__ __forceinline__ void load_stage(
    uint32_t sbase, int stage,
    const __half* __restrict__ Ahi, const __half* __restrict__ Alo,
    const __half* __restrict__ Bhi,
    int m0, int n0, int k0, int K, int tid)
{
    uint32_t base = sbase + stage * STAGE_BYTES;
#pragma unroll
    for (int h = 0; h < 2; h++) {
        int q = tid + h * 256;
        int r = q >> 2, c = q & 3;
        uint32_t so = SWZ(r, c);
        size_t ga = (size_t)(m0 + r) * K + k0 + c * 8;
        size_t gb = (size_t)(n0 + r) * K + k0 + c * 8;
        CP_ASYNC16(base + OFF_AHI + so, Ahi + ga);
        CP_ASYNC16(base + OFF_ALO + so, Alo + ga);
        CP_ASYNC16(base + OFF_BHI + so, Bhi + gb);
    }
}

__global__ __launch_bounds__(256) void gemm_hmma(
    const __half* __restrict__ Ahi, const __half* __restrict__ Alo,
    const __half* __restrict__ Bhi,
    const float* __restrict__ bias, const float* __restrict__ resid,
    float* __restrict__ C, int N, int K)
{
    extern __shared__ char sm[];
    const uint32_t sb = smem_u32(sm);
    const int tid = threadIdx.x, wid = tid >> 5, l = tid & 31;
    const int m0 = blockIdx.y * 128, n0 = blockIdx.x * 128;
    const int wm = (wid & 3) * 32, wn = (wid >> 2) * 64;

    float acc[2][8][4] = {};

    const int niter = K / 32;
    load_stage(sb, 0, Ahi, Alo, Bhi, m0, n0, 0, K, tid);
    CP_COMMIT();
    load_stage(sb, 1, Ahi, Alo, Bhi, m0, n0, 32, K, tid);
    CP_COMMIT();

    int stage = 0;
    for (int j = 0; j < niter; j++) {
        CP_WAIT1();
        __syncthreads();
        if (j + 2 < niter) {
            int s2 = stage + 2; if (s2 >= 3) s2 -= 3;
            load_stage(sb, s2, Ahi, Alo, Bhi, m0, n0, (j + 2) * 32, K, tid);
        }
        CP_COMMIT();

        const uint32_t base = sb + stage * STAGE_BYTES;
        const uint32_t abase_hi = base + OFF_AHI;
        const uint32_t abase_lo = base + OFF_ALO;
        const uint32_t bbase_hi = base + OFF_BHI;

#pragma unroll
        for (int kk = 0; kk < 2; kk++) {
            uint32_t a_hi[2][4], a_lo[2][4];
#pragma unroll
            for (int mi = 0; mi < 2; mi++) {
                int row = wm + mi * 16 + (l & 15);
                int c = kk * 2 + (l >> 4);
                LDSM4(a_hi[mi][0], a_hi[mi][1], a_hi[mi][2], a_hi[mi][3],
                      abase_hi + SWZ(row, c));
                LDSM4(a_lo[mi][0], a_lo[mi][1], a_lo[mi][2], a_lo[mi][3],
                      abase_lo + SWZ(row, c));
            }
            uint32_t b_hi[8][2];
#pragma unroll
            for (int p = 0; p < 4; p++) {
                int row = wn + p * 16 + ((l >> 4) * 8) + (l & 7);
                int c = kk * 2 + ((l >> 3) & 1);
                LDSM4(b_hi[p * 2][0], b_hi[p * 2][1], b_hi[p * 2 + 1][0], b_hi[p * 2 + 1][1],
                      bbase_hi + SWZ(row, c));
            }
#pragma unroll
            for (int mi = 0; mi < 2; mi++)
#pragma unroll
                for (int nj = 0; nj < 8; nj++)
                    MMA16816(acc[mi][nj], a_hi[mi], b_hi[nj]);
#pragma unroll
            for (int mi = 0; mi < 2; mi++)
#pragma unroll
                for (int nj = 0; nj < 8; nj++)
                    MMA16816(acc[mi][nj], a_lo[mi], b_hi[nj]);
        }
        stage++; if (stage >= 3) stage -= 3;
    }

#pragma unroll
    for (int mi = 0; mi < 2; mi++) {
#pragma unroll
        for (int nj = 0; nj < 8; nj++) {
            int row0 = m0 + wm + mi * 16 + (l >> 2);
            int col  = n0 + wn + nj * 8 + (l & 3) * 2;
            float bx = bias[col], by = bias[col + 1];
            {
                size_t o = (size_t)row0 * N + col;
                float2 v = {acc[mi][nj][0] + bx, acc[mi][nj][1] + by};
                if (resid) { float2 r = *(const float2*)(resid + o); v.x += r.x; v.y += r.y; }
                *(float2*)(C + o) = v;
            }
            {
                size_t o = (size_t)(row0 + 8) * N + col;
                float2 v = {acc[mi][nj][2] + bx, acc[mi][nj][3] + by};
                if (resid) { float2 r = *(const float2*)(resid + o); v.x += r.x; v.y += r.y; }
                *(float2*)(C + o) = v;
            }
        }
    }
}

// ---------------------------------------------------------------------------
// Prep: RoPE Q/K once, fp16 split Q (hi/lo), K/V hi, repack [b*h][s][64].
// ---------------------------------------------------------------------------
__global__ __launch_bounds__(256) void rope_split_qkv(
    const float* __restrict__ proj,
    __half* __restrict__ qh, __half* __restrict__ ql,
    __half* __restrict__ kh, __half* __restrict__ vh)
{
    const int row = blockIdx.x;            // b*2048 + s
    const int b = row >> 11, s = row & 2047;
    const float* pr = proj + (size_t)row * 4096;
    const int tid = threadIdx.x;

#pragma unroll
    for (int pp = 0; pp < 2; pp++) {
        int p = tid + pp * 256;            // 512 (h,d) pairs
        int h = p >> 5, d = p & 31;
        float inv = powf(10000.f, -(float)d / 32.f);
        float sv, cv; sincosf((float)s * inv, &sv, &cv);
        const float* Qp = pr + 2048 + h * 64 + d;
        const float* Kp = pr + 3072 + h * 64 + d;
        float q1 = Qp[0], q2 = Qp[32];
        float k1 = Kp[0], k2 = Kp[32];
        float qr1 = (q1 * cv - q2 * sv) * 0.125f;
        float qr2 = (q2 * cv + q1 * sv) * 0.125f;
        size_t o = ((size_t)(b * 16 + h) * 2048 + s) * 64 + d;
        __half t;
        t = __float2half(qr1); qh[o] = t;      ql[o]      = __float2half(qr1 - __half2float(t));
        t = __float2half(qr2); qh[o + 32] = t; ql[o + 32] = __float2half(qr2 - __half2float(t));
        kh[o]      = __float2half(k1 * cv - k2 * sv);
        kh[o + 32] = __float2half(k2 * cv + k1 * sv);
    }
    {
        int h = tid >> 4, d = (tid & 15) * 4;
        float4 v = *(const float4*)(pr + 1024 + h * 64 + d);
        __half hh[4] = {__float2half(v.x), __float2half(v.y),
                        __float2half(v.z), __float2half(v.w)};
        size_t o = ((size_t)(b * 16 + h) * 2048 + s) * 64 + d;
        *(uint2*)(vh + o) = *(uint2*)hh;
    }
}

// ---------------------------------------------------------------------------
// HMMA sigmoid attention, fp16 2-term, 128-row Q tile. 8 warps (4q x 2kv).
// Pitch 144 B rows -> conflict-free ldmatrix. smem 92160 -> 2 CTAs/SM.
// ---------------------------------------------------------------------------
#define OQH2 0
#define OQL2 18432
#define OKH2 36864
#define OVH2 46080
#define OPH2 55296
#define OPL2 73728
#define ATTN_SMEM (92160)

__global__ __launch_bounds__(256) void attn_hmma(
    const __half* __restrict__ qh, const __half* __restrict__ ql,
    const __half* __restrict__ kh, const __half* __restrict__ vh,
    float* __restrict__ out)
{
    extern __shared__ char sm[];
    const uint32_t sb = smem_u32(sm);
    const int tid = threadIdx.x, wid = tid >> 5, l = tid & 31;
    const int bh = blockIdx.x;
    const int qbi = (int)gridDim.y - 1 - (int)blockIdx.y;   // big blocks first
    const int q0 = qbi * 128;
    const size_t hbase = (size_t)bh << 17;                  // bh * 2048 * 64
    const int wq = wid & 3, wn = wid >> 2;

    // ---- load Q tiles (128 x 64 fp16, hi/lo) ----
#pragma unroll
    for (int it = 0; it < 4; it++) {
        int i = tid + it * 256;            // 1024 chunks
        int r = i >> 3, c = i & 7;
        uint32_t so = (uint32_t)(r * 144 + c * 16);
        size_t g = hbase + (size_t)(q0 + r) * 64 + c * 8;
        CP_ASYNC16(sb + OQH2 + so, qh + g);
        CP_ASYNC16(sb + OQL2 + so, ql + g);
    }
    CP_COMMIT();
    CP_WAIT0();
    __syncthreads();

    float accO[2][4][4] = {};
    const int nkb = 2 * qbi + 2;

    for (int kb = 0; kb < nkb; kb++) {
        const int k0 = kb * 64;
        // ---- load K/V tiles (hi only) ----
#pragma unroll
        for (int it = 0; it < 2; it++) {
            int i = tid + it * 256;
            int r = i >> 3, c = i & 7;
            uint32_t so = (uint32_t)(r * 144 + c * 16);
            size_t g = hbase + (size_t)(k0 + r) * 64 + c * 8;
            CP_ASYNC16(sb + OKH2 + so, kh + g);
            CP_ASYNC16(sb + OVH2 + so, vh + g);
        }
        CP_COMMIT();
        CP_WAIT0();
        __syncthreads();

        // ---- scores: (Qh + Ql) @ Kh^T ----
        float sc[2][4][4] = {};
#pragma unroll
        for (int ks = 0; ks < 4; ks++) {
            uint32_t aQh[2][4], aQl[2][4];
#pragma unroll
            for (int mi = 0; mi < 2; mi++) {
                uint32_t ro = (uint32_t)((wq * 32 + mi * 16 + (l & 15)) * 144 +
                                         (ks * 2 + (l >> 4)) * 16);
                LDSM4(aQh[mi][0], aQh[mi][1], aQh[mi][2], aQh[mi][3], sb + OQH2 + ro);
                LDSM4(aQl[mi][0], aQl[mi][1], aQl[mi][2], aQl[mi][3], sb + OQL2 + ro);
            }
            uint32_t bKh[4][2];
#pragma unroll
            for (int g2 = 0; g2 < 2; g2++) {
                int row = wn * 32 + g2 * 16 + ((l >> 4) * 8) + (l & 7);
                uint32_t ro = (uint32_t)(row * 144 + (ks * 2 + ((l >> 3) & 1)) * 16);
                LDSM4(bKh[g2 * 2][0], bKh[g2 * 2][1], bKh[g2 * 2 + 1][0], bKh[g2 * 2 + 1][1],
                      sb + OKH2 + ro);
            }
#pragma unroll
            for (int mi = 0; mi < 2; mi++)
#pragma unroll
                for (int nt = 0; nt < 4; nt++) MMA16816(sc[mi][nt], aQh[mi], bKh[nt]);
#pragma unroll
            for (int mi = 0; mi < 2; mi++)
#pragma unroll
                for (int nt = 0; nt < 4; nt++) MMA16816(sc[mi][nt], aQl[mi], bKh[nt]);
        }

        // ---- sigmoid + causal mask + fp16 split P to smem ----
        const bool edge = (kb >= 2 * qbi);
#pragma unroll
        for (int mi = 0; mi < 2; mi++) {
#pragma unroll
            for (int nt = 0; nt < 4; nt++) {
#pragma unroll
                for (int half = 0; half < 2; half++) {
                    int lq = wq * 32 + mi * 16 + (l >> 2) + half * 8;
                    int lk = wn * 32 + nt * 8 + (l & 3) * 2;
                    float p0 = __fdividef(1.f, 1.f + __expf(-sc[mi][nt][half * 2]));
                    float p1 = __fdividef(1.f, 1.f + __expf(-sc[mi][nt][half * 2 + 1]));
                    if (edge) {
                        if (k0 + lk > q0 + lq) p0 = 0.f;
                        if (k0 + lk + 1 > q0 + lq) p1 = 0.f;
                    }
                    __half h0 = __float2half(p0);
                    __half h1 = __float2half(p1);
                    __half l0 = __float2half(p0 - __half2float(h0));
                    __half l1 = __float2half(p1 - __half2float(h1));
                    uint32_t off = (uint32_t)(lq * 144 + lk * 2);
                    __half hp[2] = {h0, h1}, lp[2] = {l0, l1};
                    *(uint32_t*)(sm + OPH2 + off) = *(uint32_t*)hp;
                    *(uint32_t*)(sm + OPL2 + off) = *(uint32_t*)lp;
                }
            }
        }
        __syncthreads();

        // ---- O += (Ph + Pl) @ Vh ----
#pragma unroll
        for (int ks = 0; ks < 4; ks++) {
            uint32_t aPh[2][4], aPl[2][4];
#pragma unroll
            for (int mi = 0; mi < 2; mi++) {
                uint32_t ro = (uint32_t)((wq * 32 + mi * 16 + (l & 15)) * 144 +
                                         (ks * 2 + (l >> 4)) * 16);
                LDSM4(aPh[mi][0], aPh[mi][1], aPh[mi][2], aPh[mi][3], sb + OPH2 + ro);
                LDSM4(aPl[mi][0], aPl[mi][1], aPl[mi][2], aPl[mi][3], sb + OPL2 + ro);
            }
            uint32_t bVh[4][2];
#pragma unroll
            for (int g2 = 0; g2 < 2; g2++) {
                int row = ks * 16 + (l & 7) + ((l >> 3) & 1) * 8;
                uint32_t ro = (uint32_t)(row * 144 + wn * 64 + g2 * 32 + (l >> 4) * 16);
                LDSM4T(bVh[g2 * 2][0], bVh[g2 * 2][1], bVh[g2 * 2 + 1][0], bVh[g2 * 2 + 1][1],
                       sb + OVH2 + ro);
            }
#pragma unroll
            for (int mi = 0; mi < 2; mi++)
#pragma unroll
                for (int dt = 0; dt < 4; dt++) MMA16816(accO[mi][dt], aPh[mi], bVh[dt]);
#pragma unroll
            for (int mi = 0; mi < 2; mi++)
#pragma unroll
                for (int dt = 0; dt < 4; dt++) MMA16816(accO[mi][dt], aPl[mi], bVh[dt]);
        }
        __syncthreads();
    }

    // ---- epilogue ----
    const int b = bh >> 4, h = bh & 15;
#pragma unroll
    for (int mi = 0; mi < 2; mi++) {
#pragma unroll
        for (int dt = 0; dt < 4; dt++) {
#pragma unroll
            for (int half = 0; half < 2; half++) {
                int q = q0 + wq * 32 + mi * 16 + (l >> 2) + half * 8;
                int d = wn * 32 + dt * 8 + (l & 3) * 2;
                size_t o = ((size_t)(b * 2048 + q)) * 1024 + h * 64 + d;
                float2 v = {accO[mi][dt][half * 2], accO[mi][dt][half * 2 + 1]};
                *(float2*)(out + o) = v;
            }
        }
    }
}

// ---------------------------------------------------------------------------
// Fused LayerNorm + SiLU(U) gate -> fp16 hi/lo
// ---------------------------------------------------------------------------
__global__ __launch_bounds__(256) void ln_gate_kernel(
    const float* __restrict__ attn, const float* __restrict__ proj,
    const float* __restrict__ g, const float* __restrict__ bb,
    __half* __restrict__ ghi, __half* __restrict__ glo)
{
    const int row = blockIdx.x;
    const int tid = threadIdx.x;
    const float* a = attn + (size_t)row * H_;

    float s = 0.f, s2 = 0.f;
    for (int i = tid; i < H_; i += 256) {
        float v = a[i];
        s += v;
        s2 = fmaf(v, v, s2);
    }
    __shared__ float red[2][8];
#pragma unroll
    for (int o = 16; o; o >>= 1) {
        s  += __shfl_xor_sync(~0u, s,  o);
        s2 += __shfl_xor_sync(~0u, s2, o);
    }
    if ((tid & 31) == 0) { red[0][tid >> 5] = s; red[1][tid >> 5] = s2; }
    __syncthreads();
    if (tid < 32) {
        s  = (tid < 8) ? red[0][tid] : 0.f;
        s2 = (tid < 8) ? red[1][tid] : 0.f;
#pragma unroll
        for (int o = 4; o; o >>= 1) {
            s  += __shfl_xor_sync(~0u, s,  o);
            s2 += __shfl_xor_sync(~0u, s2, o);
        }
        if (tid == 0) { red[0][0] = s; red[1][0] = s2; }
    }
    __syncthreads();
    const float mu  = red[0][0] * (1.f / H_);
    const float var = red[1][0] * (1.f / H_) - mu * mu;
    const float rstd = rsqrtf(var + 1e-8f);

    const float* up = proj + (size_t)row * 4096;
    for (int i = tid; i < H_; i += 256) {
        float u = up[i];
        float silu = u * __fdividef(1.f, 1.f + __expf(-u));
        float v = silu * ((a[i] - mu) * rstd * g[i] + bb[i]);
        __half h = __float2half(v);
        size_t o = (size_t)row * H_ + i;
        ghi[o] = h;
        glo[o] = __float2half(v - __half2float(h));
    }
}

// ---------------------------------------------------------------------------
extern "C" void kernel_launch(void* const* d_in, const int* in_sizes, int n_in,
                              void* d_out, int out_size)
{
    const float* x   = (const float*)d_in[0];
    const float* Wp  = (const float*)d_in[2];
    const float* bp  = (const float*)d_in[3];
    const float* lng = (const float*)d_in[4];
    const float* lnb = (const float*)d_in[5];
    const float* Wt  = (const float*)d_in[6];
    const float* bt  = (const float*)d_in[7];
    float* out = (float*)d_out;

    float *proj, *attn;
    __half *xhi, *xlo, *ghi, *glo, *WpTh, *WtTh;
    __half *aqh, *aql, *akh, *avh;
    cudaGetSymbolAddress((void**)&proj, g_proj);
    cudaGetSymbolAddress((void**)&attn, g_attn);
    cudaGetSymbolAddress((void**)&xhi, g_xhi);
    cudaGetSymbolAddress((void**)&xlo, g_xlo);
    cudaGetSymbolAddress((void**)&ghi, g_ghi);
    cudaGetSymbolAddress((void**)&glo, g_glo);
    cudaGetSymbolAddress((void**)&WpTh, g_WpT_hi);
    cudaGetSymbolAddress((void**)&WtTh, g_WtT_hi);
    cudaGetSymbolAddress((void**)&aqh, g_qh);
    cudaGetSymbolAddress((void**)&aql, g_ql);
    cudaGetSymbolAddress((void**)&akh, g_kh);
    cudaGetSymbolAddress((void**)&avh, g_vh);

    cudaFuncSetAttribute(gemm_hmma,
                         cudaFuncAttributeMaxDynamicSharedMemorySize, GEMM_SMEM);
    cudaFuncSetAttribute(attn_hmma,
                         cudaFuncAttributeMaxDynamicSharedMemorySize, ATTN_SMEM);

    // 0) splits + weight transposes
    split_f32<<<(M_ * H_ / 4 + 255) / 256, 256>>>(x, xhi, xlo, M_ * H_ / 4);
    transpose_half<<<dim3(4 * H_ / 32, H_ / 32), dim3(32, 8)>>>(Wp, WpTh, H_, 4 * H_);
    transpose_half<<<dim3(H_ / 32, H_ / 32), dim3(32, 8)>>>(Wt, WtTh, H_, H_);

    // 1) proj = x @ Wp + bp   [8192, 4096]
    gemm_hmma<<<dim3(4 * H_ / 128, M_ / 128), 256, GEMM_SMEM>>>(
        xhi, xlo, WpTh, bp, nullptr, proj, 4 * H_, H_);

    // 2a) RoPE + split + repack Q/K/V
    rope_split_qkv<<<M_, 256>>>(proj, aqh, aql, akh, avh);

    // 2b) HMMA sigmoid attention -> attn [8192, 1024]
    attn_hmma<<<dim3(B_ * NH, S_ / 128), 256, ATTN_SMEM>>>(
        aqh, aql, akh, avh, attn);

    // 3) LN + SiLU gate -> fp16 hi/lo
    ln_gate_kernel<<<M_, 256>>>(attn, proj, lng, lnb, ghi, glo);

    // 4) out = x + gate @ Wt + bt
    gemm_hmma<<<dim3(H_ / 128, M_ / 128), 256, GEMM_SMEM>>>(
        ghi, glo, WtTh, bt, x, out, H_, H_);
}

// round 10
// speedup vs baseline: 7.3468x; 1.5884x over previous
#include <cuda_runtime.h>
#include <cuda_fp16.h>
#include <math.h>
#include <stdint.h>

#define B_  4
#define S_  2048
#define H_  1024
#define NH  16
#define M_  (B_ * S_)          // 8192 rows

// ------------------------- scratch (__device__ globals) --------------------
__device__ float g_proj[(size_t)M_ * 4 * H_];          // 128 MB : U|V|Q|K (fp32)
__device__ float g_attn[(size_t)M_ * H_];              // 32 MB
__device__ __half g_xh[(size_t)M_ * H_];
__device__ __half g_gh[(size_t)M_ * H_];
__device__ __half g_WpT[(size_t)4 * H_ * H_];          // Wp^T [4096,1024] fp16
__device__ __half g_WtT[(size_t)H_ * H_];              // Wt^T [1024,1024] fp16
// attention operands in [b*h][s][64] layout
__device__ __half g_qh[(size_t)M_ * H_];
__device__ __half g_kh[(size_t)M_ * H_];
__device__ __half g_vh[(size_t)M_ * H_];

// ------------------------- helpers -----------------------------------------
__device__ __forceinline__ uint32_t smem_u32(const void* p) {
    uint32_t a;
    asm("{ .reg .u64 t; cvta.to.shared.u64 t, %1; cvt.u32.u64 %0, t; }"
        : "=r"(a) : "l"(p));
    return a;
}

#define SWZ(r, c) ((uint32_t)((r) * 64 + (((c) ^ (((r) >> 1) & 3)) * 16)))

#define CP_ASYNC16(dst, src) \
    asm volatile("cp.async.cg.shared.global [%0], [%1], 16;" :: "r"(dst), "l"(src))
#define CP_COMMIT() asm volatile("cp.async.commit_group;")
#define CP_WAIT1()  asm volatile("cp.async.wait_group 1;")
#define CP_WAIT0()  asm volatile("cp.async.wait_group 0;")

#define LDSM4(r0, r1, r2, r3, addr) \
    asm volatile("ldmatrix.sync.aligned.m8n8.x4.shared.b16 {%0,%1,%2,%3}, [%4];" \
        : "=r"(r0), "=r"(r1), "=r"(r2), "=r"(r3) : "r"(addr))
#define LDSM4T(r0, r1, r2, r3, addr) \
    asm volatile("ldmatrix.sync.aligned.m8n8.x4.trans.shared.b16 {%0,%1,%2,%3}, [%4];" \
        : "=r"(r0), "=r"(r1), "=r"(r2), "=r"(r3) : "r"(addr))

#define MMA16816(d, a, b) \
    asm volatile("mma.sync.aligned.m16n8k16.row.col.f32.f16.f16.f32 " \
        "{%0,%1,%2,%3}, {%4,%5,%6,%7}, {%8,%9}, {%0,%1,%2,%3};" \
        : "+f"((d)[0]), "+f"((d)[1]), "+f"((d)[2]), "+f"((d)[3]) \
        : "r"((a)[0]), "r"((a)[1]), "r"((a)[2]), "r"((a)[3]), \
          "r"((b)[0]), "r"((b)[1]))

// ---------------------------------------------------------------------------
// convert fp32 -> fp16
// ---------------------------------------------------------------------------
__global__ __launch_bounds__(256) void conv_f16(
    const float* __restrict__ x, __half* __restrict__ hi, int n4)
{
    int i = blockIdx.x * blockDim.x + threadIdx.x;
    if (i >= n4) return;
    float4 v = ((const float4*)x)[i];
    __half h[4] = {__float2half(v.x), __float2half(v.y),
                   __float2half(v.z), __float2half(v.w)};
    ((uint2*)hi)[i] = *(uint2*)h;
}

// ---------------------------------------------------------------------------
// transpose W[K,N] -> WT[N,K] fp16
// ---------------------------------------------------------------------------
__global__ __launch_bounds__(256) void transpose_half(
    const float* __restrict__ W, __half* __restrict__ T, int K, int N)
{
    __shared__ float t[32][33];
    const int tx = threadIdx.x, ty = threadIdx.y;
    const int n0 = blockIdx.x * 32, k0 = blockIdx.y * 32;
#pragma unroll
    for (int j = 0; j < 32; j += 8)
        t[ty + j][tx] = W[(size_t)(k0 + ty + j) * N + n0 + tx];
    __syncthreads();
#pragma unroll
    for (int j = 0; j < 32; j += 8)
        T[(size_t)(n0 + ty + j) * K + k0 + tx] = __float2half(t[tx][ty + j]);
}

// ---------------------------------------------------------------------------
// HMMA GEMM fp16: C = A @ B^T + bias (+resid)
// CTA 128x128, KB=32, 3-stage cp.async pipeline.
// ---------------------------------------------------------------------------
#define STAGE_BYTES 16384
#define OFF_A 0
#define OFF_B 8192
#define GEMM_SMEM (3 * STAGE_BYTES)     // 49152

__device__ __forceinline__ void load_stage(
    uint32_t sbase, int stage,
    const __half* __restrict__ A, const __half* __restrict__ Bm,
    int m0, int n0, int k0, int K, int tid)
{
    uint32_t base = sbase + stage * STAGE_BYTES;
#pragma unroll
    for (int h = 0; h < 2; h++) {
        int q = tid + h * 256;
        int r = q >> 2, c = q & 3;
        uint32_t so = SWZ(r, c);
        size_t ga = (size_t)(m0 + r) * K + k0 + c * 8;
        size_t gb = (size_t)(n0 + r) * K + k0 + c * 8;
        CP_ASYNC16(base + OFF_A + so, A + ga);
        CP_ASYNC16(base + OFF_B + so, Bm + gb);
    }
}

__global__ __launch_bounds__(256) void gemm_hmma(
    const __half* __restrict__ A, const __half* __restrict__ Bm,
    const float* __restrict__ bias, const float* __restrict__ resid,
    float* __restrict__ C, int N, int K)
{
    extern __shared__ char sm[];
    const uint32_t sb = smem_u32(sm);
    const int tid = threadIdx.x, wid = tid >> 5, l = tid & 31;
    const int m0 = blockIdx.y * 128, n0 = blockIdx.x * 128;
    const int wm = (wid & 3) * 32, wn = (wid >> 2) * 64;

    float acc[2][8][4] = {};

    const int niter = K / 32;
    load_stage(sb, 0, A, Bm, m0, n0, 0, K, tid);
    CP_COMMIT();
    load_stage(sb, 1, A, Bm, m0, n0, 32, K, tid);
    CP_COMMIT();

    int stage = 0;
    for (int j = 0; j < niter; j++) {
        CP_WAIT1();
        __syncthreads();
        if (j + 2 < niter) {
            int s2 = stage + 2; if (s2 >= 3) s2 -= 3;
            load_stage(sb, s2, A, Bm, m0, n0, (j + 2) * 32, K, tid);
        }
        CP_COMMIT();

        const uint32_t base = sb + stage * STAGE_BYTES;
        const uint32_t abase = base + OFF_A;
        const uint32_t bbase = base + OFF_B;

#pragma unroll
        for (int kk = 0; kk < 2; kk++) {
            uint32_t a_f[2][4];
#pragma unroll
            for (int mi = 0; mi < 2; mi++) {
                int row = wm + mi * 16 + (l & 15);
                int c = kk * 2 + (l >> 4);
                LDSM4(a_f[mi][0], a_f[mi][1], a_f[mi][2], a_f[mi][3],
                      abase + SWZ(row, c));
            }
            uint32_t b_f[8][2];
#pragma unroll
            for (int p = 0; p < 4; p++) {
                int row = wn + p * 16 + ((l >> 4) * 8) + (l & 7);
                int c = kk * 2 + ((l >> 3) & 1);
                LDSM4(b_f[p * 2][0], b_f[p * 2][1], b_f[p * 2 + 1][0], b_f[p * 2 + 1][1],
                      bbase + SWZ(row, c));
            }
#pragma unroll
            for (int mi = 0; mi < 2; mi++)
#pragma unroll
                for (int nj = 0; nj < 8; nj++)
                    MMA16816(acc[mi][nj], a_f[mi], b_f[nj]);
        }
        stage++; if (stage >= 3) stage -= 3;
    }

#pragma unroll
    for (int mi = 0; mi < 2; mi++) {
#pragma unroll
        for (int nj = 0; nj < 8; nj++) {
            int row0 = m0 + wm + mi * 16 + (l >> 2);
            int col  = n0 + wn + nj * 8 + (l & 3) * 2;
            float bx = bias[col], by = bias[col + 1];
            {
                size_t o = (size_t)row0 * N + col;
                float2 v = {acc[mi][nj][0] + bx, acc[mi][nj][1] + by};
                if (resid) { float2 r = *(const float2*)(resid + o); v.x += r.x; v.y += r.y; }
                *(float2*)(C + o) = v;
            }
            {
                size_t o = (size_t)(row0 + 8) * N + col;
                float2 v = {acc[mi][nj][2] + bx, acc[mi][nj][3] + by};
                if (resid) { float2 r = *(const float2*)(resid + o); v.x += r.x; v.y += r.y; }
                *(float2*)(C + o) = v;
            }
        }
    }
}

// ---------------------------------------------------------------------------
// Prep: RoPE Q/K once, fp16 convert, repack [b*h][s][64].
// ---------------------------------------------------------------------------
__global__ __launch_bounds__(256) void rope_split_qkv(
    const float* __restrict__ proj,
    __half* __restrict__ qh, __half* __restrict__ kh, __half* __restrict__ vh)
{
    const int row = blockIdx.x;            // b*2048 + s
    const int b = row >> 11, s = row & 2047;
    const float* pr = proj + (size_t)row * 4096;
    const int tid = threadIdx.x;

#pragma unroll
    for (int pp = 0; pp < 2; pp++) {
        int p = tid + pp * 256;            // 512 (h,d) pairs
        int h = p >> 5, d = p & 31;
        float inv = powf(10000.f, -(float)d / 32.f);
        float sv, cv; sincosf((float)s * inv, &sv, &cv);
        const float* Qp = pr + 2048 + h * 64 + d;
        const float* Kp = pr + 3072 + h * 64 + d;
        float q1 = Qp[0], q2 = Qp[32];
        float k1 = Kp[0], k2 = Kp[32];
        size_t o = ((size_t)(b * 16 + h) * 2048 + s) * 64 + d;
        qh[o]      = __float2half((q1 * cv - q2 * sv) * 0.125f);
        qh[o + 32] = __float2half((q2 * cv + q1 * sv) * 0.125f);
        kh[o]      = __float2half(k1 * cv - k2 * sv);
        kh[o + 32] = __float2half(k2 * cv + k1 * sv);
    }
    {
        int h = tid >> 4, d = (tid & 15) * 4;
        float4 v = *(const float4*)(pr + 1024 + h * 64 + d);
        __half hh[4] = {__float2half(v.x), __float2half(v.y),
                        __float2half(v.z), __float2half(v.w)};
        size_t o = ((size_t)(b * 16 + h) * 2048 + s) * 64 + d;
        *(uint2*)(vh + o) = *(uint2*)hh;
    }
}

// ---------------------------------------------------------------------------
// HMMA sigmoid attention, fp16, 128-row Q tile. 8 warps (4q x 2kv).
// Pitch 144 B rows -> conflict-free ldmatrix. smem 55296 -> up to 4 CTAs/SM.
// ---------------------------------------------------------------------------
#define OQ2 0
#define OK2 18432
#define OV2 27648
#define OP2 36864
#define ATTN_SMEM (55296)

__global__ __launch_bounds__(256) void attn_hmma(
    const __half* __restrict__ qh, const __half* __restrict__ kh,
    const __half* __restrict__ vh, float* __restrict__ out)
{
    extern __shared__ char sm[];
    const uint32_t sb = smem_u32(sm);
    const int tid = threadIdx.x, wid = tid >> 5, l = tid & 31;
    const int bh = blockIdx.x;
    const int qbi = (int)gridDim.y - 1 - (int)blockIdx.y;   // big blocks first
    const int q0 = qbi * 128;
    const size_t hbase = (size_t)bh << 17;                  // bh * 2048 * 64
    const int wq = wid & 3, wn = wid >> 2;

    // ---- load Q tile (128 x 64 fp16) ----
#pragma unroll
    for (int it = 0; it < 4; it++) {
        int i = tid + it * 256;            // 1024 chunks
        int r = i >> 3, c = i & 7;
        uint32_t so = (uint32_t)(r * 144 + c * 16);
        size_t g = hbase + (size_t)(q0 + r) * 64 + c * 8;
        CP_ASYNC16(sb + OQ2 + so, qh + g);
    }
    CP_COMMIT();
    CP_WAIT0();
    __syncthreads();

    float accO[2][4][4] = {};
    const int nkb = 2 * qbi + 2;

    for (int kb = 0; kb < nkb; kb++) {
        const int k0 = kb * 64;
        // ---- load K/V tiles ----
#pragma unroll
        for (int it = 0; it < 2; it++) {
            int i = tid + it * 256;
            int r = i >> 3, c = i & 7;
            uint32_t so = (uint32_t)(r * 144 + c * 16);
            size_t g = hbase + (size_t)(k0 + r) * 64 + c * 8;
            CP_ASYNC16(sb + OK2 + so, kh + g);
            CP_ASYNC16(sb + OV2 + so, vh + g);
        }
        CP_COMMIT();
        CP_WAIT0();
        __syncthreads();

        // ---- scores: Q @ K^T ----
        float sc[2][4][4] = {};
#pragma unroll
        for (int ks = 0; ks < 4; ks++) {
            uint32_t aQ[2][4];
#pragma unroll
            for (int mi = 0; mi < 2; mi++) {
                uint32_t ro = (uint32_t)((wq * 32 + mi * 16 + (l & 15)) * 144 +
                                         (ks * 2 + (l >> 4)) * 16);
                LDSM4(aQ[mi][0], aQ[mi][1], aQ[mi][2], aQ[mi][3], sb + OQ2 + ro);
            }
            uint32_t bK[4][2];
#pragma unroll
            for (int g2 = 0; g2 < 2; g2++) {
                int row = wn * 32 + g2 * 16 + ((l >> 4) * 8) + (l & 7);
                uint32_t ro = (uint32_t)(row * 144 + (ks * 2 + ((l >> 3) & 1)) * 16);
                LDSM4(bK[g2 * 2][0], bK[g2 * 2][1], bK[g2 * 2 + 1][0], bK[g2 * 2 + 1][1],
                      sb + OK2 + ro);
            }
#pragma unroll
            for (int mi = 0; mi < 2; mi++)
#pragma unroll
                for (int nt = 0; nt < 4; nt++) MMA16816(sc[mi][nt], aQ[mi], bK[nt]);
        }

        // ---- sigmoid + causal mask + fp16 P to smem ----
        const bool edge = (kb >= 2 * qbi);
#pragma unroll
        for (int mi = 0; mi < 2; mi++) {
#pragma unroll
            for (int nt = 0; nt < 4; nt++) {
#pragma unroll
                for (int half = 0; half < 2; half++) {
                    int lq = wq * 32 + mi * 16 + (l >> 2) + half * 8;
                    int lk = wn * 32 + nt * 8 + (l & 3) * 2;
                    float p0 = __fdividef(1.f, 1.f + __expf(-sc[mi][nt][half * 2]));
                    float p1 = __fdividef(1.f, 1.f + __expf(-sc[mi][nt][half * 2 + 1]));
                    if (edge) {
                        if (k0 + lk > q0 + lq) p0 = 0.f;
                        if (k0 + lk + 1 > q0 + lq) p1 = 0.f;
                    }
                    __half hp[2] = {__float2half(p0), __float2half(p1)};
                    *(uint32_t*)(sm + OP2 + (uint32_t)(lq * 144 + lk * 2)) = *(uint32_t*)hp;
                }
            }
        }
        __syncthreads();

        // ---- O += P @ V ----
#pragma unroll
        for (int ks = 0; ks < 4; ks++) {
            uint32_t aP[2][4];
#pragma unroll
            for (int mi = 0; mi < 2; mi++) {
                uint32_t ro = (uint32_t)((wq * 32 + mi * 16 + (l & 15)) * 144 +
                                         (ks * 2 + (l >> 4)) * 16);
                LDSM4(aP[mi][0], aP[mi][1], aP[mi][2], aP[mi][3], sb + OP2 + ro);
            }
            uint32_t bV[4][2];
#pragma unroll
            for (int g2 = 0; g2 < 2; g2++) {
                int row = ks * 16 + (l & 7) + ((l >> 3) & 1) * 8;
                uint32_t ro = (uint32_t)(row * 144 + wn * 64 + g2 * 32 + (l >> 4) * 16);
                LDSM4T(bV[g2 * 2][0], bV[g2 * 2][1], bV[g2 * 2 + 1][0], bV[g2 * 2 + 1][1],
                       sb + OV2 + ro);
            }
#pragma unroll
            for (int mi = 0; mi < 2; mi++)
#pragma unroll
                for (int dt = 0; dt < 4; dt++) MMA16816(accO[mi][dt], aP[mi], bV[dt]);
        }
        __syncthreads();
    }

    // ---- epilogue ----
    const int b = bh >> 4, h = bh & 15;
#pragma unroll
    for (int mi = 0; mi < 2; mi++) {
#pragma unroll
        for (int dt = 0; dt < 4; dt++) {
#pragma unroll
            for (int half = 0; half < 2; half++) {
                int q = q0 + wq * 32 + mi * 16 + (l >> 2) + half * 8;
                int d = wn * 32 + dt * 8 + (l & 3) * 2;
                size_t o = ((size_t)(b * 2048 + q)) * 1024 + h * 64 + d;
                float2 v = {accO[mi][dt][half * 2], accO[mi][dt][half * 2 + 1]};
                *(float2*)(out + o) = v;
            }
        }
    }
}

// ---------------------------------------------------------------------------
// Fused LayerNorm + SiLU(U) gate -> fp16
// ---------------------------------------------------------------------------
__global__ __launch_bounds__(256) void ln_gate_kernel(
    const float* __restrict__ attn, const float* __restrict__ proj,
    const float* __restrict__ g, const float* __restrict__ bb,
    __half* __restrict__ gh)
{
    const int row = blockIdx.x;
    const int tid = threadIdx.x;
    const float* a = attn + (size_t)row * H_;

    float s = 0.f, s2 = 0.f;
    for (int i = tid; i < H_; i += 256) {
        float v = a[i];
        s += v;
        s2 = fmaf(v, v, s2);
    }
    __shared__ float red[2][8];
#pragma unroll
    for (int o = 16; o; o >>= 1) {
        s  += __shfl_xor_sync(~0u, s,  o);
        s2 += __shfl_xor_sync(~0u, s2, o);
    }
    if ((tid & 31) == 0) { red[0][tid >> 5] = s; red[1][tid >> 5] = s2; }
    __syncthreads();
    if (tid < 32) {
        s  = (tid < 8) ? red[0][tid] : 0.f;
        s2 = (tid < 8) ? red[1][tid] : 0.f;
#pragma unroll
        for (int o = 4; o; o >>= 1) {
            s  += __shfl_xor_sync(~0u, s,  o);
            s2 += __shfl_xor_sync(~0u, s2, o);
        }
        if (tid == 0) { red[0][0] = s; red[1][0] = s2; }
    }
    __syncthreads();
    const float mu  = red[0][0] * (1.f / H_);
    const float var = red[1][0] * (1.f / H_) - mu * mu;
    const float rstd = rsqrtf(var + 1e-8f);

    const float* up = proj + (size_t)row * 4096;
    for (int i = tid; i < H_; i += 256) {
        float u = up[i];
        float silu = u * __fdividef(1.f, 1.f + __expf(-u));
        float v = silu * ((a[i] - mu) * rstd * g[i] + bb[i]);
        gh[(size_t)row * H_ + i] = __float2half(v);
    }
}

// ---------------------------------------------------------------------------
extern "C" void kernel_launch(void* const* d_in, const int* in_sizes, int n_in,
                              void* d_out, int out_size)
{
    const float* x   = (const float*)d_in[0];
    const float* Wp  = (const float*)d_in[2];
    const float* bp  = (const float*)d_in[3];
    const float* lng = (const float*)d_in[4];
    const float* lnb = (const float*)d_in[5];
    const float* Wt  = (const float*)d_in[6];
    const float* bt  = (const float*)d_in[7];
    float* out = (float*)d_out;

    float *proj, *attn;
    __half *xh, *gh, *WpT, *WtT, *aqh, *akh, *avh;
    cudaGetSymbolAddress((void**)&proj, g_proj);
    cudaGetSymbolAddress((void**)&attn, g_attn);
    cudaGetSymbolAddress((void**)&xh, g_xh);
    cudaGetSymbolAddress((void**)&gh, g_gh);
    cudaGetSymbolAddress((void**)&WpT, g_WpT);
    cudaGetSymbolAddress((void**)&WtT, g_WtT);
    cudaGetSymbolAddress((void**)&aqh, g_qh);
    cudaGetSymbolAddress((void**)&akh, g_kh);
    cudaGetSymbolAddress((void**)&avh, g_vh);

    cudaFuncSetAttribute(gemm_hmma,
                         cudaFuncAttributeMaxDynamicSharedMemorySize, GEMM_SMEM);
    cudaFuncSetAttribute(attn_hmma,
                         cudaFuncAttributeMaxDynamicSharedMemorySize, ATTN_SMEM);

    // 0) convert + weight transposes
    conv_f16<<<(M_ * H_ / 4 + 255) / 256, 256>>>(x, xh, M_ * H_ / 4);
    transpose_half<<<dim3(4 * H_ / 32, H_ / 32), dim3(32, 8)>>>(Wp, WpT, H_, 4 * H_);
    transpose_half<<<dim3(H_ / 32, H_ / 32), dim3(32, 8)>>>(Wt, WtT, H_, H_);

    // 1) proj = x @ Wp + bp   [8192, 4096]
    gemm_hmma<<<dim3(4 * H_ / 128, M_ / 128), 256, GEMM_SMEM>>>(
        xh, WpT, bp, nullptr, proj, 4 * H_, H_);

    // 2a) RoPE + convert + repack Q/K/V
    rope_split_qkv<<<M_, 256>>>(proj, aqh, akh, avh);

    // 2b) HMMA sigmoid attention -> attn [8192, 1024]
    attn_hmma<<<dim3(B_ * NH, S_ / 128), 256, ATTN_SMEM>>>(aqh, akh, avh, attn);

    // 3) LN + SiLU gate -> fp16
    ln_gate_kernel<<<M_, 256>>>(attn, proj, lng, lnb, gh);

    // 4) out = x + gate @ Wt + bt
    gemm_hmma<<<dim3(H_ / 128, M_ / 128), 256, GEMM_SMEM>>>(
        gh, WtT, bt, x, out, H_, H_);
}

// round 12
// speedup vs baseline: 7.5963x; 1.0340x over previous
#include <cuda_runtime.h>
#include <cuda_fp16.h>
#include <math.h>
#include <stdint.h>

#define B_  4
#define S_  2048
#define H_  1024
#define NH  16
#define M_  (B_ * S_)          // 8192 rows

// ------------------------- scratch (__device__ globals) --------------------
__device__ float g_U[(size_t)M_ * H_];                 // 32 MB : U (fp32, biased)
__device__ float g_attn[(size_t)M_ * H_];              // 32 MB
__device__ __half g_xh[(size_t)M_ * H_];
__device__ __half g_gh[(size_t)M_ * H_];
__device__ __half g_WpT[(size_t)4 * H_ * H_];          // Wp^T [4096,1024] fp16
__device__ __half g_WtT[(size_t)H_ * H_];              // Wt^T [1024,1024] fp16
// attention operands in [b*h][s][64] layout
__device__ __half g_qh[(size_t)M_ * H_];
__device__ __half g_kh[(size_t)M_ * H_];
__device__ __half g_vh[(size_t)M_ * H_];

// ------------------------- helpers -----------------------------------------
__device__ __forceinline__ uint32_t smem_u32(const void* p) {
    uint32_t a;
    asm("{ .reg .u64 t; cvta.to.shared.u64 t, %1; cvt.u32.u64 %0, t; }"
        : "=r"(a) : "l"(p));
    return a;
}

#define SWZ(r, c) ((uint32_t)((r) * 64 + (((c) ^ (((r) >> 1) & 3)) * 16)))

#define CP_ASYNC16(dst, src) \
    asm volatile("cp.async.cg.shared.global [%0], [%1], 16;" :: "r"(dst), "l"(src))
#define CP_COMMIT() asm volatile("cp.async.commit_group;")
#define CP_WAIT1()  asm volatile("cp.async.wait_group 1;")
#define CP_WAIT0()  asm volatile("cp.async.wait_group 0;")

#define LDSM4(r0, r1, r2, r3, addr) \
    asm volatile("ldmatrix.sync.aligned.m8n8.x4.shared.b16 {%0,%1,%2,%3}, [%4];" \
        : "=r"(r0), "=r"(r1), "=r"(r2), "=r"(r3) : "r"(addr))
#define LDSM4T(r0, r1, r2, r3, addr) \
    asm volatile("ldmatrix.sync.aligned.m8n8.x4.trans.shared.b16 {%0,%1,%2,%3}, [%4];" \
        : "=r"(r0), "=r"(r1), "=r"(r2), "=r"(r3) : "r"(addr))

#define MMA16816(d, a, b) \
    asm volatile("mma.sync.aligned.m16n8k16.row.col.f32.f16.f16.f32 " \
        "{%0,%1,%2,%3}, {%4,%5,%6,%7}, {%8,%9}, {%0,%1,%2,%3};" \
        : "+f"((d)[0]), "+f"((d)[1]), "+f"((d)[2]), "+f"((d)[3]) \
        : "r"((a)[0]), "r"((a)[1]), "r"((a)[2]), "r"((a)[3]), \
          "r"((b)[0]), "r"((b)[1]))

// ---------------------------------------------------------------------------
// convert fp32 -> fp16
// ---------------------------------------------------------------------------
__global__ __launch_bounds__(256) void conv_f16(
    const float* __restrict__ x, __half* __restrict__ hi, int n4)
{
    int i = blockIdx.x * blockDim.x + threadIdx.x;
    if (i >= n4) return;
    float4 v = ((const float4*)x)[i];
    __half h[4] = {__float2half(v.x), __float2half(v.y),
                   __float2half(v.z), __float2half(v.w)};
    ((uint2*)hi)[i] = *(uint2*)h;
}

// ---------------------------------------------------------------------------
// transpose W[K,N] -> WT[N,K] fp16
// ---------------------------------------------------------------------------
__global__ __launch_bounds__(256) void transpose_half(
    const float* __restrict__ W, __half* __restrict__ T, int K, int N)
{
    __shared__ float t[32][33];
    const int tx = threadIdx.x, ty = threadIdx.y;
    const int n0 = blockIdx.x * 32, k0 = blockIdx.y * 32;
#pragma unroll
    for (int j = 0; j < 32; j += 8)
        t[ty + j][tx] = W[(size_t)(k0 + ty + j) * N + n0 + tx];
    __syncthreads();
#pragma unroll
    for (int j = 0; j < 32; j += 8)
        T[(size_t)(n0 + ty + j) * K + k0 + tx] = __float2half(t[tx][ty + j]);
}

// ---------------------------------------------------------------------------
// Shared GEMM mainloop: computes acc for a 128x128 tile, 3-stage cp.async.
// ---------------------------------------------------------------------------
#define STAGE_BYTES 16384
#define OFF_A 0
#define OFF_B 8192
#define GEMM_SMEM (3 * STAGE_BYTES)     // 49152

__device__ __forceinline__ void load_stage(
    uint32_t sbase, int stage,
    const __half* __restrict__ A, const __half* __restrict__ Bm,
    int m0, int n0, int k0, int K, int tid)
{
    uint32_t base = sbase + stage * STAGE_BYTES;
#pragma unroll
    for (int h = 0; h < 2; h++) {
        int q = tid + h * 256;
        int r = q >> 2, c = q & 3;
        uint32_t so = SWZ(r, c);
        size_t ga = (size_t)(m0 + r) * K + k0 + c * 8;
        size_t gb = (size_t)(n0 + r) * K + k0 + c * 8;
        CP_ASYNC16(base + OFF_A + so, A + ga);
        CP_ASYNC16(base + OFF_B + so, Bm + gb);
    }
}

__device__ __forceinline__ void gemm_mainloop(
    uint32_t sb, float acc[2][8][4],
    const __half* __restrict__ A, const __half* __restrict__ Bm,
    int m0, int n0, int K, int tid, int wid, int l)
{
    const int wm = (wid & 3) * 32, wn = (wid >> 2) * 64;
    const int niter = K / 32;
    load_stage(sb, 0, A, Bm, m0, n0, 0, K, tid);
    CP_COMMIT();
    load_stage(sb, 1, A, Bm, m0, n0, 32, K, tid);
    CP_COMMIT();

    int stage = 0;
    for (int j = 0; j < niter; j++) {
        CP_WAIT1();
        __syncthreads();
        if (j + 2 < niter) {
            int s2 = stage + 2; if (s2 >= 3) s2 -= 3;
            load_stage(sb, s2, A, Bm, m0, n0, (j + 2) * 32, K, tid);
        }
        CP_COMMIT();

        const uint32_t base = sb + stage * STAGE_BYTES;
        const uint32_t abase = base + OFF_A;
        const uint32_t bbase = base + OFF_B;

#pragma unroll
        for (int kk = 0; kk < 2; kk++) {
            uint32_t a_f[2][4];
#pragma unroll
            for (int mi = 0; mi < 2; mi++) {
                int row = wm + mi * 16 + (l & 15);
                int c = kk * 2 + (l >> 4);
                LDSM4(a_f[mi][0], a_f[mi][1], a_f[mi][2], a_f[mi][3],
                      abase + SWZ(row, c));
            }
            uint32_t b_f[8][2];
#pragma unroll
            for (int p = 0; p < 4; p++) {
                int row = wn + p * 16 + ((l >> 4) * 8) + (l & 7);
                int c = kk * 2 + ((l >> 3) & 1);
                LDSM4(b_f[p * 2][0], b_f[p * 2][1], b_f[p * 2 + 1][0], b_f[p * 2 + 1][1],
                      bbase + SWZ(row, c));
            }
#pragma unroll
            for (int mi = 0; mi < 2; mi++)
#pragma unroll
                for (int nj = 0; nj < 8; nj++)
                    MMA16816(acc[mi][nj], a_f[mi], b_f[nj]);
        }
        stage++; if (stage >= 3) stage -= 3;
    }
}

// ---------------------------------------------------------------------------
// GEMM2: out = gate @ WtT^T + bias + resid  (plain fp32 epilogue)
// ---------------------------------------------------------------------------
__global__ __launch_bounds__(256) void gemm_hmma(
    const __half* __restrict__ A, const __half* __restrict__ Bm,
    const float* __restrict__ bias, const float* __restrict__ resid,
    float* __restrict__ C, int N, int K)
{
    extern __shared__ char sm[];
    const uint32_t sb = smem_u32(sm);
    const int tid = threadIdx.x, wid = tid >> 5, l = tid & 31;
    const int m0 = blockIdx.y * 128, n0 = blockIdx.x * 128;
    const int wm = (wid & 3) * 32, wn = (wid >> 2) * 64;

    float acc[2][8][4] = {};
    gemm_mainloop(sb, acc, A, Bm, m0, n0, K, tid, wid, l);

#pragma unroll
    for (int mi = 0; mi < 2; mi++) {
#pragma unroll
        for (int nj = 0; nj < 8; nj++) {
            int row0 = m0 + wm + mi * 16 + (l >> 2);
            int col  = n0 + wn + nj * 8 + (l & 3) * 2;
            float bx = bias[col], by = bias[col + 1];
            {
                size_t o = (size_t)row0 * N + col;
                float2 v = {acc[mi][nj][0] + bx, acc[mi][nj][1] + by};
                if (resid) { float2 r = *(const float2*)(resid + o); v.x += r.x; v.y += r.y; }
                *(float2*)(C + o) = v;
            }
            {
                size_t o = (size_t)(row0 + 8) * N + col;
                float2 v = {acc[mi][nj][2] + bx, acc[mi][nj][3] + by};
                if (resid) { float2 r = *(const float2*)(resid + o); v.x += r.x; v.y += r.y; }
                *(float2*)(C + o) = v;
            }
        }
    }
}

// ---------------------------------------------------------------------------
// GEMM1 (proj) with fused epilogue:
//   region U (cols    0..1023): fp32 (acc+bias) -> Ubuf[row*1024+col]
//   region V (cols 1024..2047): fp16 (acc+bias) -> vh[(b*16+h)*2048+s][d]
//   region Q (cols 2048..3071): bias -> RoPE -> *0.125 -> fp16 qh
//   region K (cols 3072..4095): bias -> RoPE -> fp16 kh
// RoPE pair (d, d+32) lives in accumulators nj and nj+4 of the same thread.
// ---------------------------------------------------------------------------
__global__ __launch_bounds__(256) void gemm_proj(
    const __half* __restrict__ A, const __half* __restrict__ Bm,
    const float* __restrict__ bias,
    float* __restrict__ Ubuf,
    __half* __restrict__ qh, __half* __restrict__ kh, __half* __restrict__ vh,
    int N, int K)
{
    extern __shared__ char sm[];
    const uint32_t sb = smem_u32(sm);
    const int tid = threadIdx.x, wid = tid >> 5, l = tid & 31;
    const int m0 = blockIdx.y * 128, n0 = blockIdx.x * 128;
    const int wm = (wid & 3) * 32, wn = (wid >> 2) * 64;

    float acc[2][8][4] = {};
    gemm_mainloop(sb, acc, A, Bm, m0, n0, K, tid, wid, l);

    const int region = n0 >> 10;           // whole CTA in one region

    if (region == 0) {
        // ---- U: fp32 store ----
#pragma unroll
        for (int mi = 0; mi < 2; mi++)
#pragma unroll
            for (int nj = 0; nj < 8; nj++) {
                int row0 = m0 + wm + mi * 16 + (l >> 2);
                int col  = n0 + wn + nj * 8 + (l & 3) * 2;
                float bx = bias[col], by = bias[col + 1];
                *(float2*)(Ubuf + (size_t)row0 * 1024 + col) =
                    make_float2(acc[mi][nj][0] + bx, acc[mi][nj][1] + by);
                *(float2*)(Ubuf + (size_t)(row0 + 8) * 1024 + col) =
                    make_float2(acc[mi][nj][2] + bx, acc[mi][nj][3] + by);
            }
    } else if (region == 1) {
        // ---- V: fp16 repack ----
#pragma unroll
        for (int mi = 0; mi < 2; mi++)
#pragma unroll
            for (int nj = 0; nj < 8; nj++) {
                int col = n0 + wn + nj * 8 + (l & 3) * 2;
                int hd = col & 1023, h = hd >> 6, d = hd & 63;
                float bx = bias[col], by = bias[col + 1];
#pragma unroll
                for (int half = 0; half < 2; half++) {
                    int r = m0 + wm + mi * 16 + (l >> 2) + half * 8;
                    int b = r >> 11, s = r & 2047;
                    __half hv[2] = {__float2half(acc[mi][nj][half * 2] + bx),
                                    __float2half(acc[mi][nj][half * 2 + 1] + by)};
                    size_t o = ((size_t)(b * 16 + h) * 2048 + s) * 64 + d;
                    *(uint32_t*)(vh + o) = *(uint32_t*)hv;
                }
            }
    } else {
        // ---- Q or K: bias + RoPE + fp16 repack ----
        const bool isQ = (region == 2);
        __half* dst = isQ ? qh : kh;
        const float scale = isQ ? 0.125f : 1.0f;
#pragma unroll
        for (int mi = 0; mi < 2; mi++)
#pragma unroll
            for (int nj = 0; nj < 4; nj++) {
                int colA = n0 + wn + nj * 8 + (l & 3) * 2;   // d < 32
                int colB = colA + 32;
                int hd = colA & 1023, h = hd >> 6, d = hd & 63;
                float inv0 = __powf(10000.f, -(float)d / 32.f);
                float inv1 = __powf(10000.f, -(float)(d + 1) / 32.f);
                float b1a = bias[colA], b1b = bias[colA + 1];
                float b2a = bias[colB], b2b = bias[colB + 1];
#pragma unroll
                for (int half = 0; half < 2; half++) {
                    int r = m0 + wm + mi * 16 + (l >> 2) + half * 8;
                    int b = r >> 11, s = r & 2047;
                    float sv0, cv0, sv1, cv1;
                    sincosf((float)s * inv0, &sv0, &cv0);
                    sincosf((float)s * inv1, &sv1, &cv1);
                    float x1a = acc[mi][nj][half * 2]     + b1a;
                    float x1b = acc[mi][nj][half * 2 + 1] + b1b;
                    float x2a = acc[mi][nj + 4][half * 2]     + b2a;
                    float x2b = acc[mi][nj + 4][half * 2 + 1] + b2b;
                    __half lo[2] = {__float2half((x1a * cv0 - x2a * sv0) * scale),
                                    __float2half((x1b * cv1 - x2b * sv1) * scale)};
                    __half hi2[2] = {__float2half((x2a * cv0 + x1a * sv0) * scale),
                                     __float2half((x2b * cv1 + x1b * sv1) * scale)};
                    size_t o = ((size_t)(b * 16 + h) * 2048 + s) * 64 + d;
                    *(uint32_t*)(dst + o)      = *(uint32_t*)lo;
                    *(uint32_t*)(dst + o + 32) = *(uint32_t*)hi2;
                }
            }
    }
}

// ---------------------------------------------------------------------------
// HMMA sigmoid attention, fp16, 128-row Q tile. 8 warps (4q x 2kv).
// Pitch 144 B rows -> conflict-free ldmatrix. smem 55296.
// ---------------------------------------------------------------------------
#define OQ2 0
#define OK2 18432
#define OV2 27648
#define OP2 36864
#define ATTN_SMEM (55296)

__global__ __launch_bounds__(256) void attn_hmma(
    const __half* __restrict__ qh, const __half* __restrict__ kh,
    const __half* __restrict__ vh, float* __restrict__ out)
{
    extern __shared__ char sm[];
    const uint32_t sb = smem_u32(sm);
    const int tid = threadIdx.x, wid = tid >> 5, l = tid & 31;
    const int bh = blockIdx.x;
    const int qbi = (int)gridDim.y - 1 - (int)blockIdx.y;   // big blocks first
    const int q0 = qbi * 128;
    const size_t hbase = (size_t)bh << 17;                  // bh * 2048 * 64
    const int wq = wid & 3, wn = wid >> 2;

    // ---- load Q tile (128 x 64 fp16) ----
#pragma unroll
    for (int it = 0; it < 4; it++) {
        int i = tid + it * 256;            // 1024 chunks
        int r = i >> 3, c = i & 7;
        uint32_t so = (uint32_t)(r * 144 + c * 16);
        size_t g = hbase + (size_t)(q0 + r) * 64 + c * 8;
        CP_ASYNC16(sb + OQ2 + so, qh + g);
    }
    CP_COMMIT();
    CP_WAIT0();
    __syncthreads();

    float accO[2][4][4] = {};
    const int nkb = 2 * qbi + 2;

    for (int kb = 0; kb < nkb; kb++) {
        const int k0 = kb * 64;
        // ---- load K/V tiles ----
#pragma unroll
        for (int it = 0; it < 2; it++) {
            int i = tid + it * 256;
            int r = i >> 3, c = i & 7;
            uint32_t so = (uint32_t)(r * 144 + c * 16);
            size_t g = hbase + (size_t)(k0 + r) * 64 + c * 8;
            CP_ASYNC16(sb + OK2 + so, kh + g);
            CP_ASYNC16(sb + OV2 + so, vh + g);
        }
        CP_COMMIT();
        CP_WAIT0();
        __syncthreads();

        // ---- scores: Q @ K^T ----
        float sc[2][4][4] = {};
#pragma unroll
        for (int ks = 0; ks < 4; ks++) {
            uint32_t aQ[2][4];
#pragma unroll
            for (int mi = 0; mi < 2; mi++) {
                uint32_t ro = (uint32_t)((wq * 32 + mi * 16 + (l & 15)) * 144 +
                                         (ks * 2 + (l >> 4)) * 16);
                LDSM4(aQ[mi][0], aQ[mi][1], aQ[mi][2], aQ[mi][3], sb + OQ2 + ro);
            }
            uint32_t bK[4][2];
#pragma unroll
            for (int g2 = 0; g2 < 2; g2++) {
                int row = wn * 32 + g2 * 16 + ((l >> 4) * 8) + (l & 7);
                uint32_t ro = (uint32_t)(row * 144 + (ks * 2 + ((l >> 3) & 1)) * 16);
                LDSM4(bK[g2 * 2][0], bK[g2 * 2][1], bK[g2 * 2 + 1][0], bK[g2 * 2 + 1][1],
                      sb + OK2 + ro);
            }
#pragma unroll
            for (int mi = 0; mi < 2; mi++)
#pragma unroll
                for (int nt = 0; nt < 4; nt++) MMA16816(sc[mi][nt], aQ[mi], bK[nt]);
        }

        // ---- sigmoid + causal mask + fp16 P to smem ----
        const bool edge = (kb >= 2 * qbi);
#pragma unroll
        for (int mi = 0; mi < 2; mi++) {
#pragma unroll
            for (int nt = 0; nt < 4; nt++) {
#pragma unroll
                for (int half = 0; half < 2; half++) {
                    int lq = wq * 32 + mi * 16 + (l >> 2) + half * 8;
                    int lk = wn * 32 + nt * 8 + (l & 3) * 2;
                    float p0 = __fdividef(1.f, 1.f + __expf(-sc[mi][nt][half * 2]));
                    float p1 = __fdividef(1.f, 1.f + __expf(-sc[mi][nt][half * 2 + 1]));
                    if (edge) {
                        if (k0 + lk > q0 + lq) p0 = 0.f;
                        if (k0 + lk + 1 > q0 + lq) p1 = 0.f;
                    }
                    __half hp[2] = {__float2half(p0), __float2half(p1)};
                    *(uint32_t*)(sm + OP2 + (uint32_t)(lq * 144 + lk * 2)) = *(uint32_t*)hp;
                }
            }
        }
        __syncthreads();

        // ---- O += P @ V ----
#pragma unroll
        for (int ks = 0; ks < 4; ks++) {
            uint32_t aP[2][4];
#pragma unroll
            for (int mi = 0; mi < 2; mi++) {
                uint32_t ro = (uint32_t)((wq * 32 + mi * 16 + (l & 15)) * 144 +
                                         (ks * 2 + (l >> 4)) * 16);
                LDSM4(aP[mi][0], aP[mi][1], aP[mi][2], aP[mi][3], sb + OP2 + ro);
            }
            uint32_t bV[4][2];
#pragma unroll
            for (int g2 = 0; g2 < 2; g2++) {
                int row = ks * 16 + (l & 7) + ((l >> 3) & 1) * 8;
                uint32_t ro = (uint32_t)(row * 144 + wn * 64 + g2 * 32 + (l >> 4) * 16);
                LDSM4T(bV[g2 * 2][0], bV[g2 * 2][1], bV[g2 * 2 + 1][0], bV[g2 * 2 + 1][1],
                       sb + OV2 + ro);
            }
#pragma unroll
            for (int mi = 0; mi < 2; mi++)
#pragma unroll
                for (int dt = 0; dt < 4; dt++) MMA16816(accO[mi][dt], aP[mi], bV[dt]);
        }
        __syncthreads();
    }

    // ---- epilogue ----
    const int b = bh >> 4, h = bh & 15;
#pragma unroll
    for (int mi = 0; mi < 2; mi++) {
#pragma unroll
        for (int dt = 0; dt < 4; dt++) {
#pragma unroll
            for (int half = 0; half < 2; half++) {
                int q = q0 + wq * 32 + mi * 16 + (l >> 2) + half * 8;
                int d = wn * 32 + dt * 8 + (l & 3) * 2;
                size_t o = ((size_t)(b * 2048 + q)) * 1024 + h * 64 + d;
                float2 v = {accO[mi][dt][half * 2], accO[mi][dt][half * 2 + 1]};
                *(float2*)(out + o) = v;
            }
        }
    }
}

// ---------------------------------------------------------------------------
// Fused LayerNorm + SiLU(U) gate -> fp16  (U already has bias applied)
// ---------------------------------------------------------------------------
__global__ __launch_bounds__(256) void ln_gate_kernel(
    const float* __restrict__ attn, const float* __restrict__ Ubuf,
    const float* __restrict__ g, const float* __restrict__ bb,
    __half* __restrict__ gh)
{
    const int row = blockIdx.x;
    const int tid = threadIdx.x;
    const float* a = attn + (size_t)row * H_;

    float s = 0.f, s2 = 0.f;
    for (int i = tid; i < H_; i += 256) {
        float v = a[i];
        s += v;
        s2 = fmaf(v, v, s2);
    }
    __shared__ float red[2][8];
#pragma unroll
    for (int o = 16; o; o >>= 1) {
        s  += __shfl_xor_sync(~0u, s,  o);
        s2 += __shfl_xor_sync(~0u, s2, o);
    }
    if ((tid & 31) == 0) { red[0][tid >> 5] = s; red[1][tid >> 5] = s2; }
    __syncthreads();
    if (tid < 32) {
        s  = (tid < 8) ? red[0][tid] : 0.f;
        s2 = (tid < 8) ? red[1][tid] : 0.f;
#pragma unroll
        for (int o = 4; o; o >>= 1) {
            s  += __shfl_xor_sync(~0u, s,  o);
            s2 += __shfl_xor_sync(~0u, s2, o);
        }
        if (tid == 0) { red[0][0] = s; red[1][0] = s2; }
    }
    __syncthreads();
    const float mu  = red[0][0] * (1.f / H_);
    const float var = red[1][0] * (1.f / H_) - mu * mu;
    const float rstd = rsqrtf(var + 1e-8f);

    const float* up = Ubuf + (size_t)row * H_;
    for (int i = tid; i < H_; i += 256) {
        float u = up[i];
        float silu = u * __fdividef(1.f, 1.f + __expf(-u));
        float v = silu * ((a[i] - mu) * rstd * g[i] + bb[i]);
        gh[(size_t)row * H_ + i] = __float2half(v);
    }
}

// ---------------------------------------------------------------------------
extern "C" void kernel_launch(void* const* d_in, const int* in_sizes, int n_in,
                              void* d_out, int out_size)
{
    const float* x   = (const float*)d_in[0];
    const float* Wp  = (const float*)d_in[2];
    const float* bp  = (const float*)d_in[3];
    const float* lng = (const float*)d_in[4];
    const float* lnb = (const float*)d_in[5];
    const float* Wt  = (const float*)d_in[6];
    const float* bt  = (const float*)d_in[7];
    float* out = (float*)d_out;

    float *Ubuf, *attn;
    __half *xh, *gh, *WpT, *WtT, *aqh, *akh, *avh;
    cudaGetSymbolAddress((void**)&Ubuf, g_U);
    cudaGetSymbolAddress((void**)&attn, g_attn);
    cudaGetSymbolAddress((void**)&xh, g_xh);
    cudaGetSymbolAddress((void**)&gh, g_gh);
    cudaGetSymbolAddress((void**)&WpT, g_WpT);
    cudaGetSymbolAddress((void**)&WtT, g_WtT);
    cudaGetSymbolAddress((void**)&aqh, g_qh);
    cudaGetSymbolAddress((void**)&akh, g_kh);
    cudaGetSymbolAddress((void**)&avh, g_vh);

    cudaFuncSetAttribute(gemm_hmma,
                         cudaFuncAttributeMaxDynamicSharedMemorySize, GEMM_SMEM);
    cudaFuncSetAttribute(gemm_proj,
                         cudaFuncAttributeMaxDynamicSharedMemorySize, GEMM_SMEM);
    cudaFuncSetAttribute(attn_hmma,
                         cudaFuncAttributeMaxDynamicSharedMemorySize, ATTN_SMEM);

    // 0) convert + weight transposes
    conv_f16<<<(M_ * H_ / 4 + 255) / 256, 256>>>(x, xh, M_ * H_ / 4);
    transpose_half<<<dim3(4 * H_ / 32, H_ / 32), dim3(32, 8)>>>(Wp, WpT, H_, 4 * H_);
    transpose_half<<<dim3(H_ / 32, H_ / 32), dim3(32, 8)>>>(Wt, WtT, H_, H_);

    // 1) proj GEMM with fused bias + RoPE + fp16 repack epilogue
    gemm_proj<<<dim3(4 * H_ / 128, M_ / 128), 256, GEMM_SMEM>>>(
        xh, WpT, bp, Ubuf, aqh, akh, avh, 4 * H_, H_);

    // 2) HMMA sigmoid attention -> attn [8192, 1024]
    attn_hmma<<<dim3(B_ * NH, S_ / 128), 256, ATTN_SMEM>>>(aqh, akh, avh, attn);

    // 3) LN + SiLU gate -> fp16
    ln_gate_kernel<<<M_, 256>>>(attn, Ubuf, lng, lnb, gh);

    // 4) out = x + gate @ Wt + bt
    gemm_hmma<<<dim3(H_ / 128, M_ / 128), 256, GEMM_SMEM>>>(
        gh, WtT, bt, x, out, H_, H_);
}